// round 11
// baseline (speedup 1.0000x reference)
#include <cuda_runtime.h>
#include <cuda_bf16.h>
#include <math.h>
#include <stdint.h>

// Problem constants: B=8, N=4096, C=768, H=8, D=96
constexpr int M_TOK = 8 * 4096;   // 32768 tokens
constexpr int K_IN  = 768;        // C

// ---- device scratch (allocation-free rule: __device__ globals) ----
__device__ __align__(16) __nv_bfloat16 g_Wrh[96 * 768];  // hi(w1*sum_h Wv_rgb)
__device__ __align__(16) __nv_bfloat16 g_Wrl[96 * 768];  // lo
__device__ __align__(16) __nv_bfloat16 g_Wdh[96 * 768];  // hi(w0*sum_h Wv_depth)
__device__ __align__(16) __nv_bfloat16 g_Wdl[96 * 768];
__device__ __align__(16) __nv_bfloat16 g_Wfh[768 * 96];  // hi(sum_q Wout folded)
__device__ __align__(16) __nv_bfloat16 g_Wfl[768 * 96];
__device__ float g_bg[96];                                // combined bias for g

// ============================================================
// Helpers (plain sm_103-safe PTX: ldmatrix + mma.sync + cp.async)
// ============================================================
__device__ __forceinline__ uint32_t smem_u32(const void* p) {
    uint32_t a;
    asm("{ .reg .u64 t; cvta.to.shared.u64 t, %1; cvt.u32.u64 %0, t; }" : "=r"(a) : "l"(p));
    return a;
}
__device__ __forceinline__ void ldsm4(uint32_t* r, uint32_t addr) {
    asm volatile("ldmatrix.sync.aligned.m8n8.x4.shared.b16 {%0,%1,%2,%3}, [%4];"
                 : "=r"(r[0]), "=r"(r[1]), "=r"(r[2]), "=r"(r[3]) : "r"(addr));
}
__device__ __forceinline__ void mma16816(float* c, const uint32_t* a, const uint32_t* b) {
    asm("mma.sync.aligned.m16n8k16.row.col.f32.bf16.bf16.f32 "
        "{%0,%1,%2,%3}, {%4,%5,%6,%7}, {%8,%9}, {%0,%1,%2,%3};"
        : "+f"(c[0]), "+f"(c[1]), "+f"(c[2]), "+f"(c[3])
        : "r"(a[0]), "r"(a[1]), "r"(a[2]), "r"(a[3]), "r"(b[0]), "r"(b[1]));
}
__device__ __forceinline__ void cpa8(uint32_t d, const void* s) {
    asm volatile("cp.async.ca.shared.global [%0], [%1], 8;" :: "r"(d), "l"(s));
}
__device__ __forceinline__ void cpa16(uint32_t d, const void* s) {
    asm volatile("cp.async.cg.shared.global [%0], [%1], 16;" :: "r"(d), "l"(s));
}
#define CPA_COMMIT() asm volatile("cp.async.commit_group;" ::: "memory")
#define CPA_WAIT0()  asm volatile("cp.async.wait_group 0;" ::: "memory")

__device__ __forceinline__ void splitbf(float v, __nv_bfloat16& h, __nv_bfloat16& l) {
    h = __float2bfloat16_rn(v);
    l = __float2bfloat16_rn(v - __bfloat162float(h));
}
// Fast RZ split of TWO floats -> (hi bf16x2, lo bf16x2).
__device__ __forceinline__ void split2(float x, float y, uint32_t& hi2, uint32_t& lo2) {
    uint32_t bx = __float_as_uint(x), by = __float_as_uint(y);
    hi2 = __byte_perm(bx, by, 0x7632);                 // {hi(x), hi(y)}
    float hx = __uint_as_float(bx & 0xFFFF0000u);
    float hy = __uint_as_float(by & 0xFFFF0000u);
    asm("cvt.rn.bf16x2.f32 %0, %1, %2;" : "=r"(lo2) : "f"(y - hy), "f"(x - hx));
}
// XOR swizzle on 16B chunks: conflict-free ldmatrix for 64B/192B rows
__device__ __forceinline__ uint32_t swz(uint32_t row, uint32_t chunk) {
    return chunk ^ ((row >> 1) & 3);
}

// ============================================================
// Prep: fold heads, sigmoid weights, split to bf16 hi/lo (RN)
// ============================================================
__global__ void prep_kernel(const float* __restrict__ W1, const float* __restrict__ b1,
                            const float* __restrict__ W2, const float* __restrict__ b2,
                            const float* __restrict__ Wout, const float* __restrict__ aw)
{
    int idx = blockIdx.x * blockDim.x + threadIdx.x;   // 0 .. 73727
    float w0 = 1.0f / (1.0f + expf(-aw[0]));
    float w1 = 1.0f / (1.0f + expf(-aw[1]));

    if (idx < 96 * 768) {
        int d = idx / 768;
        int c = idx - d * 768;
        float sr = 0.0f, sd = 0.0f;
#pragma unroll
        for (int h = 0; h < 8; h++) {
            sr += W1[(size_t)(1536 + h * 96 + d) * 768 + c];
            sd += W2[(size_t)(768  + h * 96 + d) * 768 + c];
        }
        __nv_bfloat16 h16, l16;
        splitbf(w1 * sr, h16, l16); g_Wrh[idx] = h16; g_Wrl[idx] = l16;
        splitbf(w0 * sd, h16, l16); g_Wdh[idx] = h16; g_Wdl[idx] = l16;
    }
    if (idx < 768 * 96) {
        int c = idx / 96;
        int d = idx - c * 96;
        float s = 0.0f;
#pragma unroll
        for (int q = 0; q < 8; q++) s += Wout[(size_t)c * 768 + q * 96 + d];
        __nv_bfloat16 h16, l16;
        splitbf(s, h16, l16); g_Wfh[idx] = h16; g_Wfl[idx] = l16;
    }
    if (idx < 96) {
        float sbr = 0.0f, sbd = 0.0f;
#pragma unroll
        for (int h = 0; h < 8; h++) {
            sbr += b1[1536 + h * 96 + idx];
            sbd += b2[768  + h * 96 + idx];
        }
        g_bg[idx] = w0 * sbd + w1 * sbr;
    }
}

// ============================================================
// FUSED kernel, CTA tile 64x96 (8 warps, warp tile 16x48),
// __launch_bounds__(256,3) -> 24 warps/SM. R8 loop structure.
//  Phase 1: G = Xr@Wr^T + Xd@Wd^T + bg  (K=1536, 48 stages of 32)
//           + fused x_rgb passthrough. G kept in SMEM (hi/lo).
//  Phase 2: Y = G @ Wf^T + bout, 12 Wf tiles of 64 cols.
// smem: phase1 2x20480=40960 | phase2 G 24576 + B 2x24576 = 73728.
// ============================================================
constexpr uint32_t GST  = 20480;                 // one BK=32 stage (64-row A)
constexpr uint32_t G_AL = 4096, G_BH = 8192, G_BL = 14336;
constexpr int G_STAGES  = 48;                    // 1536 / 32

constexpr uint32_t P2_GL  = 12288;   // G lo offset (G hi at 0); 64 rows x 192B
constexpr uint32_t P2_B   = 24576;   // B buffers start
constexpr uint32_t P2_BSZ = 24576;   // per B buffer (Bh 12K + Bl 12K)
constexpr uint32_t P2_BL  = 12288;   // Bl offset within a B buffer
constexpr int FUSED_SMEM  = 73728;

__global__ __launch_bounds__(256, 3) void fused_gemm(const float* __restrict__ Xr,
                                                     const float* __restrict__ Xd,
                                                     float* __restrict__ out_rgb,
                                                     const float* __restrict__ bout,
                                                     float* __restrict__ Y)
{
    extern __shared__ char dsm[];
    const uint32_t sbase = smem_u32(dsm);

    const int tid   = threadIdx.x;
    const int lane  = tid & 31;
    const int wid   = tid >> 5;
    const int warpM = wid >> 1;      // 0..3 (16-row slices)
    const int warpN = wid & 1;       // 0..1 (48-col slices)
    const int bm    = blockIdx.x << 6;   // 64 rows per CTA

    // ======================= PHASE 1 =======================
    float acc[6][4];
#pragma unroll
    for (int j = 0; j < 6; j++)
#pragma unroll
        for (int q = 0; q < 4; q++) acc[j][q] = 0.0f;

    const int arow0 = tid >> 3;          // + 32*l, l<2  (A: 64 rows x 8 float4-cols)
    const int ac4   = tid & 7;
    const int brow0 = tid >> 3;          // + 32*l, l<3  (B: 96 rows x 8 uint2-cols)
    const int bu    = tid & 7;

    const uint32_t a_sts_sw = (swz((uint32_t)arow0, (uint32_t)(ac4 >> 1)) << 4) + (ac4 & 1) * 8;
    const uint32_t b_sts_sw = (swz((uint32_t)brow0, (uint32_t)(bu >> 1)) << 4) + (bu & 1) * 8;

    const uint32_t a_row = (uint32_t)(warpM * 16 + (lane & 15));
    const uint32_t a_ck0 = (uint32_t)(lane >> 4);
    const uint32_t b_row = (uint32_t)(warpN * 48 + (lane & 7) + ((lane >> 4) << 3));
    const uint32_t b_ck0 = (uint32_t)((lane >> 3) & 1);

    float4 av[2];

    // ---- prologue: stage 0 (rgb, kb = 0) ----
#pragma unroll
    for (int l = 0; l < 2; l++)
        av[l] = *reinterpret_cast<const float4*>(
            Xr + (size_t)(bm + arow0 + 32 * l) * 768 + (ac4 << 2));
#pragma unroll
    for (int l = 0; l < 3; l++) {
        uint32_t row = (uint32_t)(brow0 + 32 * l);
        cpa8(sbase + G_BH + row * 64 + b_sts_sw, g_Wrh + (size_t)row * 768 + (bu << 2));
        cpa8(sbase + G_BL + row * 64 + b_sts_sw, g_Wrl + (size_t)row * 768 + (bu << 2));
    }
    CPA_COMMIT();
#pragma unroll
    for (int l = 0; l < 2; l++) {
        uint32_t ro = (uint32_t)(arow0 + 32 * l) * 64;
        uint32_t h01, l01, h23, l23;
        split2(av[l].x, av[l].y, h01, l01);
        split2(av[l].z, av[l].w, h23, l23);
        *reinterpret_cast<uint2*>(dsm + ro + a_sts_sw)        = make_uint2(h01, h23);
        *reinterpret_cast<uint2*>(dsm + G_AL + ro + a_sts_sw) = make_uint2(l01, l23);
        *reinterpret_cast<float4*>(
            out_rgb + (size_t)(bm + arow0 + 32 * l) * 768 + (ac4 << 2)) = av[l];
    }
    CPA_WAIT0();
    __syncthreads();

    for (int s = 0; s < G_STAGES; s++) {
        const int sn = s + 1;
        if (sn < G_STAGES) {
            const float* X = (sn < 24) ? Xr : Xd;
            const __nv_bfloat16* BH = (sn < 24) ? g_Wrh : g_Wdh;
            const __nv_bfloat16* BL = (sn < 24) ? g_Wrl : g_Wdl;
            const int kb = ((sn < 24) ? sn : (sn - 24)) << 5;
            const uint32_t bo = (uint32_t)(sn & 1) * GST;
#pragma unroll
            for (int l = 0; l < 2; l++)
                av[l] = *reinterpret_cast<const float4*>(
                    X + (size_t)(bm + arow0 + 32 * l) * 768 + kb + (ac4 << 2));
#pragma unroll
            for (int l = 0; l < 3; l++) {
                uint32_t row = (uint32_t)(brow0 + 32 * l);
                size_t gi = (size_t)row * 768 + kb + (bu << 2);
                cpa8(sbase + bo + G_BH + row * 64 + b_sts_sw, BH + gi);
                cpa8(sbase + bo + G_BL + row * 64 + b_sts_sw, BL + gi);
            }
            CPA_COMMIT();
        }

        // ---- compute stage s ----
        {
            const uint32_t sb = sbase + (uint32_t)(s & 1) * GST;
#pragma unroll
            for (int kk = 0; kk < 2; kk++) {
                uint32_t ah[4], al[4];
                {
                    uint32_t addr = sb + a_row * 64 + (swz(a_row, kk * 2 + a_ck0) << 4);
                    ldsm4(ah, addr);
                    ldsm4(al, addr + G_AL);
                }
                uint32_t bh2[3][4], bl2[3][4];
#pragma unroll
                for (int ng = 0; ng < 3; ng++) {
                    uint32_t row = b_row + ng * 16;
                    uint32_t addr = sb + G_BH + row * 64 + (swz(row, kk * 2 + b_ck0) << 4);
                    ldsm4(bh2[ng], addr);
                    ldsm4(bl2[ng], addr + (G_BL - G_BH));
                }
#pragma unroll
                for (int nt = 0; nt < 6; nt++)
                    mma16816(acc[nt], ah, &bh2[nt >> 1][(nt & 1) * 2]);
#pragma unroll
                for (int nt = 0; nt < 6; nt++)
                    mma16816(acc[nt], ah, &bl2[nt >> 1][(nt & 1) * 2]);
#pragma unroll
                for (int nt = 0; nt < 6; nt++)
                    mma16816(acc[nt], al, &bh2[nt >> 1][(nt & 1) * 2]);
            }
        }

        if (sn < G_STAGES) {
            char* st = dsm + (sn & 1) * GST;
            const int kb = ((sn < 24) ? sn : (sn - 24)) << 5;
#pragma unroll
            for (int l = 0; l < 2; l++) {
                uint32_t ro = (uint32_t)(arow0 + 32 * l) * 64;
                uint32_t h01, l01, h23, l23;
                split2(av[l].x, av[l].y, h01, l01);
                split2(av[l].z, av[l].w, h23, l23);
                *reinterpret_cast<uint2*>(st + ro + a_sts_sw)        = make_uint2(h01, h23);
                *reinterpret_cast<uint2*>(st + G_AL + ro + a_sts_sw) = make_uint2(l01, l23);
            }
            if (sn < 24) {
#pragma unroll
                for (int l = 0; l < 2; l++)
                    *reinterpret_cast<float4*>(
                        out_rgb + (size_t)(bm + arow0 + 32 * l) * 768 + kb + (ac4 << 2)) = av[l];
            }
            CPA_WAIT0();
        }
        __syncthreads();
    }

    // ============== PHASE 1 -> 2 TRANSITION ==============
    // Prefetch B tile 0 (cols 0..63 of Wf) into B buffer 0.
#pragma unroll
    for (int l = 0; l < 3; l++) {
        int f = tid + (l << 8);
        int r = f / 12, u = f - r * 12;
        uint32_t so = (uint32_t)r * 192 + (swz((uint32_t)r, (uint32_t)u) << 4);
        cpa16(sbase + P2_B + so,         g_Wfh + (size_t)r * 96 + (u << 3));
        cpa16(sbase + P2_B + P2_BL + so, g_Wfl + (size_t)r * 96 + (u << 3));
    }
    CPA_COMMIT();

    // Write G block (hi/lo, bias added) into smem [0, 24576).
    {
        uint32_t r0 = (uint32_t)(warpM * 16 + (lane >> 2));
#pragma unroll
        for (int nt = 0; nt < 6; nt++) {
            int n = warpN * 48 + nt * 8 + (lane & 3) * 2;
            float b0 = g_bg[n], b1 = g_bg[n + 1];
            float v0 = acc[nt][0] + b0, v1 = acc[nt][1] + b1;
            float v2 = acc[nt][2] + b0, v3 = acc[nt][3] + b1;
            uint32_t u = (uint32_t)(warpN * 6 + nt);
            uint32_t off = (uint32_t)((lane & 3) << 2);
            uint32_t ad0 = r0 * 192 + (swz(r0, u) << 4) + off;
            uint32_t ad1 = (r0 + 8) * 192 + (swz(r0 + 8, u) << 4) + off;
            uint32_t h2, l2;
            split2(v0, v1, h2, l2);
            *reinterpret_cast<uint32_t*>(dsm + ad0)         = h2;
            *reinterpret_cast<uint32_t*>(dsm + P2_GL + ad0) = l2;
            split2(v2, v3, h2, l2);
            *reinterpret_cast<uint32_t*>(dsm + ad1)         = h2;
            *reinterpret_cast<uint32_t*>(dsm + P2_GL + ad1) = l2;
        }
    }
    CPA_WAIT0();
    __syncthreads();

    // ======================= PHASE 2 =======================
    // Warp tile 16x32; 12 B tiles of 64 cols.
    const uint32_t p2b_row = (uint32_t)(warpN * 32 + (lane & 7) + ((lane >> 4) << 3));
    const uint32_t p2b_ck0 = (uint32_t)((lane >> 3) & 1);

    for (int i = 0; i < 12; i++) {
        if (i + 1 < 12) {
            const int cn = (i + 1) << 6;
            const uint32_t bo = P2_B + (uint32_t)((i + 1) & 1) * P2_BSZ;
#pragma unroll
            for (int l = 0; l < 3; l++) {
                int f = tid + (l << 8);
                int r = f / 12, u = f - r * 12;
                uint32_t so = (uint32_t)r * 192 + (swz((uint32_t)r, (uint32_t)u) << 4);
                cpa16(sbase + bo + so,         g_Wfh + (size_t)(cn + r) * 96 + (u << 3));
                cpa16(sbase + bo + P2_BL + so, g_Wfl + (size_t)(cn + r) * 96 + (u << 3));
            }
            CPA_COMMIT();
        }

        float acc2[4][4];
#pragma unroll
        for (int j = 0; j < 4; j++)
#pragma unroll
            for (int q = 0; q < 4; q++) acc2[j][q] = 0.0f;

        const uint32_t bbase = sbase + P2_B + (uint32_t)(i & 1) * P2_BSZ;
#pragma unroll
        for (int ks = 0; ks < 6; ks++) {
            uint32_t ah[4], al[4];
            {
                uint32_t addr = sbase + a_row * 192 + (swz(a_row, ks * 2 + a_ck0) << 4);
                ldsm4(ah, addr);
                ldsm4(al, addr + P2_GL);
            }
            uint32_t bh2[2][4], bl2[2][4];
#pragma unroll
            for (int ng = 0; ng < 2; ng++) {
                uint32_t row = p2b_row + ng * 16;
                uint32_t addr = bbase + row * 192 + (swz(row, ks * 2 + p2b_ck0) << 4);
                ldsm4(bh2[ng], addr);
                ldsm4(bl2[ng], addr + P2_BL);
            }
#pragma unroll
            for (int nt = 0; nt < 4; nt++)
                mma16816(acc2[nt], ah, &bh2[nt >> 1][(nt & 1) * 2]);
#pragma unroll
            for (int nt = 0; nt < 4; nt++)
                mma16816(acc2[nt], ah, &bl2[nt >> 1][(nt & 1) * 2]);
#pragma unroll
            for (int nt = 0; nt < 4; nt++)
                mma16816(acc2[nt], al, &bh2[nt >> 1][(nt & 1) * 2]);
        }

        // epilogue tile i
        {
            int m0 = bm + warpM * 16 + (lane >> 2);
#pragma unroll
            for (int nt = 0; nt < 4; nt++) {
                int n = (i << 6) + warpN * 32 + nt * 8 + (lane & 3) * 2;
                float b0 = bout[n], b1 = bout[n + 1];
                *reinterpret_cast<float2*>(Y + (size_t)m0 * 768 + n) =
                    make_float2(acc2[nt][0] + b0, acc2[nt][1] + b1);
                *reinterpret_cast<float2*>(Y + (size_t)(m0 + 8) * 768 + n) =
                    make_float2(acc2[nt][2] + b0, acc2[nt][3] + b1);
            }
        }

        if (i + 1 < 12) CPA_WAIT0();
        __syncthreads();
    }
}

// ============================================================
extern "C" void kernel_launch(void* const* d_in, const int* in_sizes, int n_in,
                              void* d_out, int out_size)
{
    const float* x_rgb   = (const float*)d_in[0];
    const float* x_depth = (const float*)d_in[1];
    const float* W1      = (const float*)d_in[2];
    const float* b1      = (const float*)d_in[3];
    const float* W2      = (const float*)d_in[4];
    const float* b2      = (const float*)d_in[5];
    const float* Wout    = (const float*)d_in[6];
    const float* bout    = (const float*)d_in[7];
    const float* aw      = (const float*)d_in[8];

    float* out_rgb = (float*)d_out;
    float* out_fus = out_rgb + (size_t)M_TOK * K_IN;   // second half: x_fusion

    static bool attr_done = false;
    if (!attr_done) {
        cudaFuncSetAttribute(fused_gemm, cudaFuncAttributeMaxDynamicSharedMemorySize,
                             FUSED_SMEM);
        attr_done = true;
    }

    prep_kernel<<<288, 256>>>(W1, b1, W2, b2, Wout, aw);
    fused_gemm<<<M_TOK / 64, 256, FUSED_SMEM>>>(x_rgb, x_depth, out_rgb, bout, out_fus);
}

// round 12
// speedup vs baseline: 2.0767x; 2.0767x over previous
#include <cuda_runtime.h>
#include <cuda_fp16.h>
#include <math.h>
#include <stdint.h>

// Problem constants: B=8, N=4096, C=768, H=8, D=96
constexpr int M_TOK = 8 * 4096;   // 32768 tokens
constexpr int K_IN  = 768;        // C

// ---- device scratch (allocation-free rule: __device__ globals) ----
// Weights stored as SINGLE fp16 (RN). A-side operands get 2-term hi/lo splits.
__device__ __align__(16) __half g_Wr[96 * 768];   // fp16(w1 * sum_h Wv_rgb)
__device__ __align__(16) __half g_Wd[96 * 768];   // fp16(w0 * sum_h Wv_depth)
__device__ __align__(16) __half g_Wf[768 * 96];   // fp16(sum_q Wout folded)
__device__ float g_bg[96];                         // combined bias for g

// ============================================================
// Helpers (plain sm_103-safe PTX: ldmatrix + mma.sync + cp.async)
// ============================================================
__device__ __forceinline__ uint32_t smem_u32(const void* p) {
    uint32_t a;
    asm("{ .reg .u64 t; cvta.to.shared.u64 t, %1; cvt.u32.u64 %0, t; }" : "=r"(a) : "l"(p));
    return a;
}
__device__ __forceinline__ void ldsm4(uint32_t* r, uint32_t addr) {
    asm volatile("ldmatrix.sync.aligned.m8n8.x4.shared.b16 {%0,%1,%2,%3}, [%4];"
                 : "=r"(r[0]), "=r"(r[1]), "=r"(r[2]), "=r"(r[3]) : "r"(addr));
}
__device__ __forceinline__ void mma16816(float* c, const uint32_t* a, const uint32_t* b) {
    asm("mma.sync.aligned.m16n8k16.row.col.f32.f16.f16.f32 "
        "{%0,%1,%2,%3}, {%4,%5,%6,%7}, {%8,%9}, {%0,%1,%2,%3};"
        : "+f"(c[0]), "+f"(c[1]), "+f"(c[2]), "+f"(c[3])
        : "r"(a[0]), "r"(a[1]), "r"(a[2]), "r"(a[3]), "r"(b[0]), "r"(b[1]));
}
__device__ __forceinline__ void cpa16(uint32_t d, const void* s) {
    asm volatile("cp.async.cg.shared.global [%0], [%1], 16;" :: "r"(d), "l"(s));
}
#define CPA_COMMIT() asm volatile("cp.async.commit_group;" ::: "memory")
#define CPA_WAIT0()  asm volatile("cp.async.wait_group 0;" ::: "memory")

// Split TWO floats into fp16 hi pair + fp16 residual pair (RN both).
// x -> low half, y -> high half (matches ldmatrix k-pair ordering).
__device__ __forceinline__ void split2h(float x, float y, uint32_t& hi2, uint32_t& lo2) {
    __half2 h = __floats2half2_rn(x, y);
    hi2 = *reinterpret_cast<uint32_t*>(&h);
    float2 hf = __half22float2(h);
    __half2 l = __floats2half2_rn(x - hf.x, y - hf.y);
    lo2 = *reinterpret_cast<uint32_t*>(&l);
}
// XOR swizzle on 16B chunks: conflict-free ldmatrix for 64B/192B rows
__device__ __forceinline__ uint32_t swz(uint32_t row, uint32_t chunk) {
    return chunk ^ ((row >> 1) & 3);
}

// ============================================================
// Prep: fold heads, sigmoid weights, round to fp16 (RN)
// ============================================================
__global__ void prep_kernel(const float* __restrict__ W1, const float* __restrict__ b1,
                            const float* __restrict__ W2, const float* __restrict__ b2,
                            const float* __restrict__ Wout, const float* __restrict__ aw)
{
    int idx = blockIdx.x * blockDim.x + threadIdx.x;   // 0 .. 73727
    float w0 = 1.0f / (1.0f + expf(-aw[0]));
    float w1 = 1.0f / (1.0f + expf(-aw[1]));

    if (idx < 96 * 768) {
        int d = idx / 768;
        int c = idx - d * 768;
        float sr = 0.0f, sd = 0.0f;
#pragma unroll
        for (int h = 0; h < 8; h++) {
            sr += W1[(size_t)(1536 + h * 96 + d) * 768 + c];
            sd += W2[(size_t)(768  + h * 96 + d) * 768 + c];
        }
        g_Wr[idx] = __float2half_rn(w1 * sr);
        g_Wd[idx] = __float2half_rn(w0 * sd);
    }
    if (idx < 768 * 96) {
        int c = idx / 96;
        int d = idx - c * 96;
        float s = 0.0f;
#pragma unroll
        for (int q = 0; q < 8; q++) s += Wout[(size_t)c * 768 + q * 96 + d];
        g_Wf[idx] = __float2half_rn(s);
    }
    if (idx < 96) {
        float sbr = 0.0f, sbd = 0.0f;
#pragma unroll
        for (int h = 0; h < 8; h++) {
            sbr += b1[1536 + h * 96 + idx];
            sbd += b2[768  + h * 96 + idx];
        }
        g_bg[idx] = w0 * sbd + w1 * sbr;
    }
}

// ============================================================
// FUSED kernel, CTA tile 128x96, 8 warps (4M x 2N), occ 2 (R8 base).
// fp16 2-term: per k-step  AhB + AlB  (B single fp16).
//  Phase 1: G = Xr@Wr^T + Xd@Wd^T + bg (48 stages of BK=32)
//           + fused x_rgb passthrough. G kept in SMEM (fp16 hi/lo).
//  Phase 2: Y = G @ Wf^T + bout, 6 Wf tiles of 128 cols.
// smem: phase1 2x22528=45056 | phase2 G 49152 + B 2x24576 = 98304.
// ============================================================
constexpr uint32_t GST  = 22528;                 // Ah 8K | Al 8K | B 6K
constexpr uint32_t G_AL = 8192, G_B = 16384;
constexpr int G_STAGES  = 48;                    // 1536 / 32

constexpr uint32_t P2_GL  = 24576;   // G lo (G hi at 0); 128 rows x 192B each
constexpr uint32_t P2_B   = 49152;   // B buffers start
constexpr uint32_t P2_BSZ = 24576;   // per B buffer: 128 Wf rows x 192B, single fp16
constexpr int FUSED_SMEM  = 98304;

__global__ __launch_bounds__(256, 2) void fused_gemm(const float* __restrict__ Xr,
                                                     const float* __restrict__ Xd,
                                                     float* __restrict__ out_rgb,
                                                     const float* __restrict__ bout,
                                                     float* __restrict__ Y)
{
    extern __shared__ char dsm[];
    const uint32_t sbase = smem_u32(dsm);

    const int tid   = threadIdx.x;
    const int lane  = tid & 31;
    const int wid   = tid >> 5;
    const int warpM = wid >> 1;      // 0..3
    const int warpN = wid & 1;       // 0..1
    const int bm    = blockIdx.x << 7;

    // ======================= PHASE 1 =======================
    float acc[2][6][4];
#pragma unroll
    for (int i = 0; i < 2; i++)
#pragma unroll
        for (int j = 0; j < 6; j++)
#pragma unroll
            for (int q = 0; q < 4; q++) acc[i][j][q] = 0.0f;

    const int arow0 = tid >> 3;          // + 32*l  (A: 128 rows x 8 float4-cols)
    const int ac4   = tid & 7;

    const uint32_t a_sts_sw = (swz((uint32_t)arow0, (uint32_t)(ac4 >> 1)) << 4) + (ac4 & 1) * 8;

    const uint32_t a_row = (uint32_t)(warpM * 32 + (lane & 15));
    const uint32_t a_ck0 = (uint32_t)(lane >> 4);
    const uint32_t b_row = (uint32_t)(warpN * 48 + (lane & 7) + ((lane >> 4) << 3));
    const uint32_t b_ck0 = (uint32_t)((lane >> 3) & 1);

    float4 av[4];

    // ---- prologue: stage 0 (rgb, kb = 0) ----
#pragma unroll
    for (int l = 0; l < 4; l++)
        av[l] = *reinterpret_cast<const float4*>(
            Xr + (size_t)(bm + arow0 + 32 * l) * 768 + (ac4 << 2));
    // B stage 0: 96 rows x 4 16B-chunks = 384 cpa16
#pragma unroll
    for (int l = 0; l < 2; l++) {
        int f = tid + (l << 8);
        if (f < 384) {
            uint32_t r = (uint32_t)(f >> 2), c = (uint32_t)(f & 3);
            cpa16(sbase + G_B + r * 64 + (swz(r, c) << 4),
                  g_Wr + (size_t)r * 768 + (c << 3));
        }
    }
    CPA_COMMIT();
#pragma unroll
    for (int l = 0; l < 4; l++) {
        uint32_t ro = (uint32_t)(arow0 + 32 * l) * 64;
        uint32_t h01, l01, h23, l23;
        split2h(av[l].x, av[l].y, h01, l01);
        split2h(av[l].z, av[l].w, h23, l23);
        *reinterpret_cast<uint2*>(dsm + ro + a_sts_sw)        = make_uint2(h01, h23);
        *reinterpret_cast<uint2*>(dsm + G_AL + ro + a_sts_sw) = make_uint2(l01, l23);
        *reinterpret_cast<float4*>(
            out_rgb + (size_t)(bm + arow0 + 32 * l) * 768 + (ac4 << 2)) = av[l];
    }
    CPA_WAIT0();
    __syncthreads();

    for (int s = 0; s < G_STAGES; s++) {
        const int sn = s + 1;
        if (sn < G_STAGES) {
            const float* X = (sn < 24) ? Xr : Xd;
            const __half* BW = (sn < 24) ? g_Wr : g_Wd;
            const int kb = ((sn < 24) ? sn : (sn - 24)) << 5;
            const uint32_t bo = (uint32_t)(sn & 1) * GST;
#pragma unroll
            for (int l = 0; l < 4; l++)
                av[l] = *reinterpret_cast<const float4*>(
                    X + (size_t)(bm + arow0 + 32 * l) * 768 + kb + (ac4 << 2));
#pragma unroll
            for (int l = 0; l < 2; l++) {
                int f = tid + (l << 8);
                if (f < 384) {
                    uint32_t r = (uint32_t)(f >> 2), c = (uint32_t)(f & 3);
                    cpa16(sbase + bo + G_B + r * 64 + (swz(r, c) << 4),
                          BW + (size_t)r * 768 + kb + (c << 3));
                }
            }
            CPA_COMMIT();
        }

        // ---- compute stage s ----
        {
            const uint32_t sb = sbase + (uint32_t)(s & 1) * GST;
#pragma unroll
            for (int kk = 0; kk < 2; kk++) {
                uint32_t ah[2][4], al[2][4];
#pragma unroll
                for (int mt = 0; mt < 2; mt++) {
                    uint32_t row = a_row + mt * 16;
                    uint32_t addr = sb + row * 64 + (swz(row, kk * 2 + a_ck0) << 4);
                    ldsm4(ah[mt], addr);
                    ldsm4(al[mt], addr + G_AL);
                }
                uint32_t b2[3][4];
#pragma unroll
                for (int ng = 0; ng < 3; ng++) {
                    uint32_t row = b_row + ng * 16;
                    ldsm4(b2[ng], sb + G_B + row * 64 + (swz(row, kk * 2 + b_ck0) << 4));
                }
#pragma unroll
                for (int mt = 0; mt < 2; mt++)
#pragma unroll
                    for (int nt = 0; nt < 6; nt++)
                        mma16816(acc[mt][nt], ah[mt], &b2[nt >> 1][(nt & 1) * 2]);
#pragma unroll
                for (int mt = 0; mt < 2; mt++)
#pragma unroll
                    for (int nt = 0; nt < 6; nt++)
                        mma16816(acc[mt][nt], al[mt], &b2[nt >> 1][(nt & 1) * 2]);
            }
        }

        if (sn < G_STAGES) {
            char* st = dsm + (sn & 1) * GST;
            const int kb = ((sn < 24) ? sn : (sn - 24)) << 5;
#pragma unroll
            for (int l = 0; l < 4; l++) {
                uint32_t ro = (uint32_t)(arow0 + 32 * l) * 64;
                uint32_t h01, l01, h23, l23;
                split2h(av[l].x, av[l].y, h01, l01);
                split2h(av[l].z, av[l].w, h23, l23);
                *reinterpret_cast<uint2*>(st + ro + a_sts_sw)        = make_uint2(h01, h23);
                *reinterpret_cast<uint2*>(st + G_AL + ro + a_sts_sw) = make_uint2(l01, l23);
            }
            if (sn < 24) {
#pragma unroll
                for (int l = 0; l < 4; l++)
                    *reinterpret_cast<float4*>(
                        out_rgb + (size_t)(bm + arow0 + 32 * l) * 768 + kb + (ac4 << 2)) = av[l];
            }
            CPA_WAIT0();
        }
        __syncthreads();
    }

    // ============== PHASE 1 -> 2 TRANSITION ==============
    // Prefetch B tile 0 (Wf rows 0..127) into B buffer 0: 1536 cpa16.
#pragma unroll
    for (int l = 0; l < 6; l++) {
        int f = tid + (l << 8);
        int r = f / 12, u = f - r * 12;
        cpa16(sbase + P2_B + (uint32_t)r * 192 + (swz((uint32_t)r, (uint32_t)u) << 4),
              g_Wf + (size_t)r * 96 + (u << 3));
    }
    CPA_COMMIT();

    // Write G block (fp16 hi/lo, bias added) into smem [0, 49152).
#pragma unroll
    for (int mt = 0; mt < 2; mt++) {
        uint32_t r0 = (uint32_t)(warpM * 32 + mt * 16 + (lane >> 2));
#pragma unroll
        for (int nt = 0; nt < 6; nt++) {
            int n = warpN * 48 + nt * 8 + (lane & 3) * 2;
            float b0 = g_bg[n], b1 = g_bg[n + 1];
            float v0 = acc[mt][nt][0] + b0, v1 = acc[mt][nt][1] + b1;
            float v2 = acc[mt][nt][2] + b0, v3 = acc[mt][nt][3] + b1;
            uint32_t u = (uint32_t)(warpN * 6 + nt);
            uint32_t off = (uint32_t)((lane & 3) << 2);
            uint32_t ad0 = r0 * 192 + (swz(r0, u) << 4) + off;
            uint32_t ad1 = (r0 + 8) * 192 + (swz(r0 + 8, u) << 4) + off;
            uint32_t h2, l2;
            split2h(v0, v1, h2, l2);
            *reinterpret_cast<uint32_t*>(dsm + ad0)         = h2;
            *reinterpret_cast<uint32_t*>(dsm + P2_GL + ad0) = l2;
            split2h(v2, v3, h2, l2);
            *reinterpret_cast<uint32_t*>(dsm + ad1)         = h2;
            *reinterpret_cast<uint32_t*>(dsm + P2_GL + ad1) = l2;
        }
    }
    CPA_WAIT0();
    __syncthreads();

    // ======================= PHASE 2 =======================
    // 6 Wf tiles of 128 cols; warp tile 32 rows x 64 cols (nt=8).
    const uint32_t p2b_row = (uint32_t)(warpN * 64 + (lane & 7) + ((lane >> 4) << 3));
    const uint32_t p2b_ck0 = (uint32_t)((lane >> 3) & 1);

    for (int i = 0; i < 6; i++) {
        if (i + 1 < 6) {
            const int cn = (i + 1) << 7;
            const uint32_t bo = P2_B + (uint32_t)((i + 1) & 1) * P2_BSZ;
#pragma unroll
            for (int l = 0; l < 6; l++) {
                int f = tid + (l << 8);
                int r = f / 12, u = f - r * 12;
                cpa16(sbase + bo + (uint32_t)r * 192 + (swz((uint32_t)r, (uint32_t)u) << 4),
                      g_Wf + (size_t)(cn + r) * 96 + (u << 3));
            }
            CPA_COMMIT();
        }

        float acc2[2][8][4];
#pragma unroll
        for (int a = 0; a < 2; a++)
#pragma unroll
            for (int j = 0; j < 8; j++)
#pragma unroll
                for (int q = 0; q < 4; q++) acc2[a][j][q] = 0.0f;

        const uint32_t bbase = sbase + P2_B + (uint32_t)(i & 1) * P2_BSZ;
#pragma unroll
        for (int ks = 0; ks < 6; ks++) {
            uint32_t ah[2][4], al[2][4];
#pragma unroll
            for (int mt = 0; mt < 2; mt++) {
                uint32_t row = a_row + mt * 16;
                uint32_t addr = sbase + row * 192 + (swz(row, ks * 2 + a_ck0) << 4);
                ldsm4(ah[mt], addr);
                ldsm4(al[mt], addr + P2_GL);
            }
            uint32_t b2[4][4];
#pragma unroll
            for (int ng = 0; ng < 4; ng++) {
                uint32_t row = p2b_row + ng * 16;
                ldsm4(b2[ng], bbase + row * 192 + (swz(row, ks * 2 + p2b_ck0) << 4));
            }
#pragma unroll
            for (int mt = 0; mt < 2; mt++)
#pragma unroll
                for (int nt = 0; nt < 8; nt++)
                    mma16816(acc2[mt][nt], ah[mt], &b2[nt >> 1][(nt & 1) * 2]);
#pragma unroll
            for (int mt = 0; mt < 2; mt++)
#pragma unroll
                for (int nt = 0; nt < 8; nt++)
                    mma16816(acc2[mt][nt], al[mt], &b2[nt >> 1][(nt & 1) * 2]);
        }

        // epilogue tile i
#pragma unroll
        for (int mt = 0; mt < 2; mt++) {
            int m0 = bm + warpM * 32 + mt * 16 + (lane >> 2);
#pragma unroll
            for (int nt = 0; nt < 8; nt++) {
                int n = (i << 7) + warpN * 64 + nt * 8 + (lane & 3) * 2;
                float b0 = bout[n], b1 = bout[n + 1];
                *reinterpret_cast<float2*>(Y + (size_t)m0 * 768 + n) =
                    make_float2(acc2[mt][nt][0] + b0, acc2[mt][nt][1] + b1);
                *reinterpret_cast<float2*>(Y + (size_t)(m0 + 8) * 768 + n) =
                    make_float2(acc2[mt][nt][2] + b0, acc2[mt][nt][3] + b1);
            }
        }

        if (i + 1 < 6) CPA_WAIT0();
        __syncthreads();
    }
}

// ============================================================
extern "C" void kernel_launch(void* const* d_in, const int* in_sizes, int n_in,
                              void* d_out, int out_size)
{
    const float* x_rgb   = (const float*)d_in[0];
    const float* x_depth = (const float*)d_in[1];
    const float* W1      = (const float*)d_in[2];
    const float* b1      = (const float*)d_in[3];
    const float* W2      = (const float*)d_in[4];
    const float* b2      = (const float*)d_in[5];
    const float* Wout    = (const float*)d_in[6];
    const float* bout    = (const float*)d_in[7];
    const float* aw      = (const float*)d_in[8];

    float* out_rgb = (float*)d_out;
    float* out_fus = out_rgb + (size_t)M_TOK * K_IN;   // second half: x_fusion

    static bool attr_done = false;
    if (!attr_done) {
        cudaFuncSetAttribute(fused_gemm, cudaFuncAttributeMaxDynamicSharedMemorySize,
                             FUSED_SMEM);
        attr_done = true;
    }

    prep_kernel<<<288, 256>>>(W1, b1, W2, b2, Wout, aw);
    fused_gemm<<<M_TOK / 128, 256, FUSED_SMEM>>>(x_rgb, x_depth, out_rgb, bout, out_fus);
}

// round 13
// speedup vs baseline: 2.1713x; 1.0455x over previous
#include <cuda_runtime.h>
#include <cuda_fp16.h>
#include <math.h>
#include <stdint.h>

// Problem constants: B=8, N=4096, C=768, H=8, D=96
constexpr int M_TOK = 8 * 4096;   // 32768 tokens
constexpr int K_IN  = 768;        // C

// ---- device scratch (allocation-free rule: __device__ globals) ----
__device__ __align__(16) __half g_Wr[96 * 768];   // fp16(w1 * sum_h Wv_rgb)
__device__ __align__(16) __half g_Wd[96 * 768];   // fp16(w0 * sum_h Wv_depth)
__device__ __align__(16) __half g_Wf[768 * 96];   // fp16(sum_q Wout folded)
__device__ float g_bg[96];                         // combined bias for g

// ============================================================
// Helpers (plain sm_103-safe PTX: ldmatrix + mma.sync + cp.async)
// ============================================================
__device__ __forceinline__ uint32_t smem_u32(const void* p) {
    uint32_t a;
    asm("{ .reg .u64 t; cvta.to.shared.u64 t, %1; cvt.u32.u64 %0, t; }" : "=r"(a) : "l"(p));
    return a;
}
__device__ __forceinline__ void ldsm4(uint32_t* r, uint32_t addr) {
    asm volatile("ldmatrix.sync.aligned.m8n8.x4.shared.b16 {%0,%1,%2,%3}, [%4];"
                 : "=r"(r[0]), "=r"(r[1]), "=r"(r[2]), "=r"(r[3]) : "r"(addr));
}
__device__ __forceinline__ void mma16816(float* c, const uint32_t* a, const uint32_t* b) {
    asm("mma.sync.aligned.m16n8k16.row.col.f32.f16.f16.f32 "
        "{%0,%1,%2,%3}, {%4,%5,%6,%7}, {%8,%9}, {%0,%1,%2,%3};"
        : "+f"(c[0]), "+f"(c[1]), "+f"(c[2]), "+f"(c[3])
        : "r"(a[0]), "r"(a[1]), "r"(a[2]), "r"(a[3]), "r"(b[0]), "r"(b[1]));
}
__device__ __forceinline__ void cpa16(uint32_t d, const void* s) {
    asm volatile("cp.async.cg.shared.global [%0], [%1], 16;" :: "r"(d), "l"(s));
}
#define CPA_COMMIT() asm volatile("cp.async.commit_group;" ::: "memory")
#define CPA_WAIT0()  asm volatile("cp.async.wait_group 0;" ::: "memory")

// Split TWO floats into fp16 hi pair + fp16 residual pair (RN both).
__device__ __forceinline__ void split2h(float x, float y, uint32_t& hi2, uint32_t& lo2) {
    __half2 h = __floats2half2_rn(x, y);
    hi2 = *reinterpret_cast<uint32_t*>(&h);
    float2 hf = __half22float2(h);
    __half2 l = __floats2half2_rn(x - hf.x, y - hf.y);
    lo2 = *reinterpret_cast<uint32_t*>(&l);
}
// XOR swizzle on 16B chunks: conflict-free ldmatrix for 64B/192B rows
__device__ __forceinline__ uint32_t swz(uint32_t row, uint32_t chunk) {
    return chunk ^ ((row >> 1) & 3);
}

// ============================================================
// Prep: fold heads, sigmoid weights, round to fp16 (RN)
// ============================================================
__global__ void prep_kernel(const float* __restrict__ W1, const float* __restrict__ b1,
                            const float* __restrict__ W2, const float* __restrict__ b2,
                            const float* __restrict__ Wout, const float* __restrict__ aw)
{
    int idx = blockIdx.x * blockDim.x + threadIdx.x;   // 0 .. 73727
    float w0 = 1.0f / (1.0f + expf(-aw[0]));
    float w1 = 1.0f / (1.0f + expf(-aw[1]));

    if (idx < 96 * 768) {
        int d = idx / 768;
        int c = idx - d * 768;
        float sr = 0.0f, sd = 0.0f;
#pragma unroll
        for (int h = 0; h < 8; h++) {
            sr += W1[(size_t)(1536 + h * 96 + d) * 768 + c];
            sd += W2[(size_t)(768  + h * 96 + d) * 768 + c];
        }
        g_Wr[idx] = __float2half_rn(w1 * sr);
        g_Wd[idx] = __float2half_rn(w0 * sd);
    }
    if (idx < 768 * 96) {
        int c = idx / 96;
        int d = idx - c * 96;
        float s = 0.0f;
#pragma unroll
        for (int q = 0; q < 8; q++) s += Wout[(size_t)c * 768 + q * 96 + d];
        g_Wf[idx] = __float2half_rn(s);
    }
    if (idx < 96) {
        float sbr = 0.0f, sbd = 0.0f;
#pragma unroll
        for (int h = 0; h < 8; h++) {
            sbr += b1[1536 + h * 96 + idx];
            sbd += b2[768  + h * 96 + idx];
        }
        g_bg[idx] = w0 * sbd + w1 * sbr;
    }
}

// ============================================================
// FUSED kernel. R12: CTA 64x96, 128 threads (4 warps, warp tile
// 32x48 — IDENTICAL per-warp geometry to R11), occ 4 -> grid 512
// covers all 148 SMs in one wave with 3-4 independent CTAs/SM.
//  Phase 1: G = Xr@Wr^T + Xd@Wd^T + bg (48 stages of BK=32)
//           + fused x_rgb passthrough. G kept in SMEM (fp16 hi/lo).
//  Phase 2: Y = G @ Wf^T + bout, 12 Wf tiles of 64 cols.
// smem/CTA: phase1 2x14336=28672 | phase2 12K G hi + 12K G lo
//           + 2x12K B = 49152.  4 x 49152 = 196608 <= SM smem.
// ============================================================
constexpr uint32_t GST  = 14336;                 // Ah 4K | Al 4K | B 6K
constexpr uint32_t G_AL = 4096, G_B = 8192;
constexpr int G_STAGES  = 48;                    // 1536 / 32

constexpr uint32_t P2_GL  = 12288;   // G lo (G hi at 0); 64 rows x 192B each
constexpr uint32_t P2_B   = 24576;   // B buffers start
constexpr uint32_t P2_BSZ = 12288;   // per B buffer: 64 Wf rows x 192B
constexpr int FUSED_SMEM  = 49152;

__global__ __launch_bounds__(128, 4) void fused_gemm(const float* __restrict__ Xr,
                                                     const float* __restrict__ Xd,
                                                     float* __restrict__ out_rgb,
                                                     const float* __restrict__ bout,
                                                     float* __restrict__ Y)
{
    extern __shared__ char dsm[];
    const uint32_t sbase = smem_u32(dsm);

    const int tid   = threadIdx.x;
    const int lane  = tid & 31;
    const int wid   = tid >> 5;
    const int warpM = wid >> 1;      // 0..1 (32-row slices)
    const int warpN = wid & 1;       // 0..1 (48-col slices)
    const int bm    = blockIdx.x << 6;   // 64 rows per CTA

    // ======================= PHASE 1 =======================
    float acc[2][6][4];
#pragma unroll
    for (int i = 0; i < 2; i++)
#pragma unroll
        for (int j = 0; j < 6; j++)
#pragma unroll
            for (int q = 0; q < 4; q++) acc[i][j][q] = 0.0f;

    const int arow0 = tid >> 3;          // + 16*l, l<4  (A: 64 rows x 8 float4-cols)
    const int ac4   = tid & 7;

    // swz is invariant under row += 16 (bit shifts out of (row>>1)&3 range)
    const uint32_t a_sts_sw = (swz((uint32_t)arow0, (uint32_t)(ac4 >> 1)) << 4) + (ac4 & 1) * 8;

    const uint32_t a_row = (uint32_t)(warpM * 32 + (lane & 15));
    const uint32_t a_ck0 = (uint32_t)(lane >> 4);
    const uint32_t b_row = (uint32_t)(warpN * 48 + (lane & 7) + ((lane >> 4) << 3));
    const uint32_t b_ck0 = (uint32_t)((lane >> 3) & 1);

    float4 av[4];

    // ---- prologue: stage 0 (rgb, kb = 0) ----
#pragma unroll
    for (int l = 0; l < 4; l++)
        av[l] = *reinterpret_cast<const float4*>(
            Xr + (size_t)(bm + arow0 + 16 * l) * 768 + (ac4 << 2));
    // B stage 0: 96 rows x 4 16B-chunks = 384 cpa16, 3/thread
#pragma unroll
    for (int l = 0; l < 3; l++) {
        int f = tid + (l << 7);
        uint32_t r = (uint32_t)(f >> 2), c = (uint32_t)(f & 3);
        cpa16(sbase + G_B + r * 64 + (swz(r, c) << 4),
              g_Wr + (size_t)r * 768 + (c << 3));
    }
    CPA_COMMIT();
#pragma unroll
    for (int l = 0; l < 4; l++) {
        uint32_t ro = (uint32_t)(arow0 + 16 * l) * 64;
        uint32_t h01, l01, h23, l23;
        split2h(av[l].x, av[l].y, h01, l01);
        split2h(av[l].z, av[l].w, h23, l23);
        *reinterpret_cast<uint2*>(dsm + ro + a_sts_sw)        = make_uint2(h01, h23);
        *reinterpret_cast<uint2*>(dsm + G_AL + ro + a_sts_sw) = make_uint2(l01, l23);
        *reinterpret_cast<float4*>(
            out_rgb + (size_t)(bm + arow0 + 16 * l) * 768 + (ac4 << 2)) = av[l];
    }
    CPA_WAIT0();
    __syncthreads();

    for (int s = 0; s < G_STAGES; s++) {
        const int sn = s + 1;
        if (sn < G_STAGES) {
            const float* X = (sn < 24) ? Xr : Xd;
            const __half* BW = (sn < 24) ? g_Wr : g_Wd;
            const int kb = ((sn < 24) ? sn : (sn - 24)) << 5;
            const uint32_t bo = (uint32_t)(sn & 1) * GST;
#pragma unroll
            for (int l = 0; l < 4; l++)
                av[l] = *reinterpret_cast<const float4*>(
                    X + (size_t)(bm + arow0 + 16 * l) * 768 + kb + (ac4 << 2));
#pragma unroll
            for (int l = 0; l < 3; l++) {
                int f = tid + (l << 7);
                uint32_t r = (uint32_t)(f >> 2), c = (uint32_t)(f & 3);
                cpa16(sbase + bo + G_B + r * 64 + (swz(r, c) << 4),
                      BW + (size_t)r * 768 + kb + (c << 3));
            }
            CPA_COMMIT();
        }

        // ---- compute stage s ----
        {
            const uint32_t sb = sbase + (uint32_t)(s & 1) * GST;
#pragma unroll
            for (int kk = 0; kk < 2; kk++) {
                uint32_t ah[2][4], al[2][4];
#pragma unroll
                for (int mt = 0; mt < 2; mt++) {
                    uint32_t row = a_row + mt * 16;
                    uint32_t addr = sb + row * 64 + (swz(row, kk * 2 + a_ck0) << 4);
                    ldsm4(ah[mt], addr);
                    ldsm4(al[mt], addr + G_AL);
                }
                uint32_t b2[3][4];
#pragma unroll
                for (int ng = 0; ng < 3; ng++) {
                    uint32_t row = b_row + ng * 16;
                    ldsm4(b2[ng], sb + G_B + row * 64 + (swz(row, kk * 2 + b_ck0) << 4));
                }
#pragma unroll
                for (int mt = 0; mt < 2; mt++)
#pragma unroll
                    for (int nt = 0; nt < 6; nt++)
                        mma16816(acc[mt][nt], ah[mt], &b2[nt >> 1][(nt & 1) * 2]);
#pragma unroll
                for (int mt = 0; mt < 2; mt++)
#pragma unroll
                    for (int nt = 0; nt < 6; nt++)
                        mma16816(acc[mt][nt], al[mt], &b2[nt >> 1][(nt & 1) * 2]);
            }
        }

        if (sn < G_STAGES) {
            char* st = dsm + (sn & 1) * GST;
            const int kb = ((sn < 24) ? sn : (sn - 24)) << 5;
#pragma unroll
            for (int l = 0; l < 4; l++) {
                uint32_t ro = (uint32_t)(arow0 + 16 * l) * 64;
                uint32_t h01, l01, h23, l23;
                split2h(av[l].x, av[l].y, h01, l01);
                split2h(av[l].z, av[l].w, h23, l23);
                *reinterpret_cast<uint2*>(st + ro + a_sts_sw)        = make_uint2(h01, h23);
                *reinterpret_cast<uint2*>(st + G_AL + ro + a_sts_sw) = make_uint2(l01, l23);
            }
            if (sn < 24) {
#pragma unroll
                for (int l = 0; l < 4; l++)
                    *reinterpret_cast<float4*>(
                        out_rgb + (size_t)(bm + arow0 + 16 * l) * 768 + kb + (ac4 << 2)) = av[l];
            }
            CPA_WAIT0();
        }
        __syncthreads();
    }

    // ============== PHASE 1 -> 2 TRANSITION ==============
    // Prefetch B tile 0 (Wf rows 0..63) into B buffer 0: 768 cpa16, 6/thread.
#pragma unroll
    for (int l = 0; l < 6; l++) {
        int f = tid + (l << 7);
        int r = f / 12, u = f - r * 12;
        cpa16(sbase + P2_B + (uint32_t)r * 192 + (swz((uint32_t)r, (uint32_t)u) << 4),
              g_Wf + (size_t)r * 96 + (u << 3));
    }
    CPA_COMMIT();

    // Write G block (fp16 hi/lo, bias added) into smem [0, 24576).
#pragma unroll
    for (int mt = 0; mt < 2; mt++) {
        uint32_t r0 = (uint32_t)(warpM * 32 + mt * 16 + (lane >> 2));
#pragma unroll
        for (int nt = 0; nt < 6; nt++) {
            int n = warpN * 48 + nt * 8 + (lane & 3) * 2;
            float b0 = g_bg[n], b1 = g_bg[n + 1];
            float v0 = acc[mt][nt][0] + b0, v1 = acc[mt][nt][1] + b1;
            float v2 = acc[mt][nt][2] + b0, v3 = acc[mt][nt][3] + b1;
            uint32_t u = (uint32_t)(warpN * 6 + nt);
            uint32_t off = (uint32_t)((lane & 3) << 2);
            uint32_t ad0 = r0 * 192 + (swz(r0, u) << 4) + off;
            uint32_t ad1 = (r0 + 8) * 192 + (swz(r0 + 8, u) << 4) + off;
            uint32_t h2, l2;
            split2h(v0, v1, h2, l2);
            *reinterpret_cast<uint32_t*>(dsm + ad0)         = h2;
            *reinterpret_cast<uint32_t*>(dsm + P2_GL + ad0) = l2;
            split2h(v2, v3, h2, l2);
            *reinterpret_cast<uint32_t*>(dsm + ad1)         = h2;
            *reinterpret_cast<uint32_t*>(dsm + P2_GL + ad1) = l2;
        }
    }
    CPA_WAIT0();
    __syncthreads();

    // ======================= PHASE 2 =======================
    // 12 Wf tiles of 64 cols; warp tile 32 rows x 32 cols (nt=4).
    const uint32_t p2b_row = (uint32_t)(warpN * 32 + (lane & 7) + ((lane >> 4) << 3));
    const uint32_t p2b_ck0 = (uint32_t)((lane >> 3) & 1);

    for (int i = 0; i < 12; i++) {
        if (i + 1 < 12) {
            const int cn = (i + 1) << 6;
            const uint32_t bo = P2_B + (uint32_t)((i + 1) & 1) * P2_BSZ;
#pragma unroll
            for (int l = 0; l < 6; l++) {
                int f = tid + (l << 7);
                int r = f / 12, u = f - r * 12;
                cpa16(sbase + bo + (uint32_t)r * 192 + (swz((uint32_t)r, (uint32_t)u) << 4),
                      g_Wf + (size_t)(cn + r) * 96 + (u << 3));
            }
            CPA_COMMIT();
        }

        float acc2[2][4][4];
#pragma unroll
        for (int a = 0; a < 2; a++)
#pragma unroll
            for (int j = 0; j < 4; j++)
#pragma unroll
                for (int q = 0; q < 4; q++) acc2[a][j][q] = 0.0f;

        const uint32_t bbase = sbase + P2_B + (uint32_t)(i & 1) * P2_BSZ;
#pragma unroll
        for (int ks = 0; ks < 6; ks++) {
            uint32_t ah[2][4], al[2][4];
#pragma unroll
            for (int mt = 0; mt < 2; mt++) {
                uint32_t row = a_row + mt * 16;
                uint32_t addr = sbase + row * 192 + (swz(row, ks * 2 + a_ck0) << 4);
                ldsm4(ah[mt], addr);
                ldsm4(al[mt], addr + P2_GL);
            }
            uint32_t b2[2][4];
#pragma unroll
            for (int ng = 0; ng < 2; ng++) {
                uint32_t row = p2b_row + ng * 16;
                ldsm4(b2[ng], bbase + row * 192 + (swz(row, ks * 2 + p2b_ck0) << 4));
            }
#pragma unroll
            for (int mt = 0; mt < 2; mt++)
#pragma unroll
                for (int nt = 0; nt < 4; nt++)
                    mma16816(acc2[mt][nt], ah[mt], &b2[nt >> 1][(nt & 1) * 2]);
#pragma unroll
            for (int mt = 0; mt < 2; mt++)
#pragma unroll
                for (int nt = 0; nt < 4; nt++)
                    mma16816(acc2[mt][nt], al[mt], &b2[nt >> 1][(nt & 1) * 2]);
        }

        // epilogue tile i
#pragma unroll
        for (int mt = 0; mt < 2; mt++) {
            int m0 = bm + warpM * 32 + mt * 16 + (lane >> 2);
#pragma unroll
            for (int nt = 0; nt < 4; nt++) {
                int n = (i << 6) + warpN * 32 + nt * 8 + (lane & 3) * 2;
                float b0 = bout[n], b1 = bout[n + 1];
                *reinterpret_cast<float2*>(Y + (size_t)m0 * 768 + n) =
                    make_float2(acc2[mt][nt][0] + b0, acc2[mt][nt][1] + b1);
                *reinterpret_cast<float2*>(Y + (size_t)(m0 + 8) * 768 + n) =
                    make_float2(acc2[mt][nt][2] + b0, acc2[mt][nt][3] + b1);
            }
        }

        if (i + 1 < 12) CPA_WAIT0();
        __syncthreads();
    }
}

// ============================================================
extern "C" void kernel_launch(void* const* d_in, const int* in_sizes, int n_in,
                              void* d_out, int out_size)
{
    const float* x_rgb   = (const float*)d_in[0];
    const float* x_depth = (const float*)d_in[1];
    const float* W1      = (const float*)d_in[2];
    const float* b1      = (const float*)d_in[3];
    const float* W2      = (const float*)d_in[4];
    const float* b2      = (const float*)d_in[5];
    const float* Wout    = (const float*)d_in[6];
    const float* bout    = (const float*)d_in[7];
    const float* aw      = (const float*)d_in[8];

    float* out_rgb = (float*)d_out;
    float* out_fus = out_rgb + (size_t)M_TOK * K_IN;   // second half: x_fusion

    static bool attr_done = false;
    if (!attr_done) {
        cudaFuncSetAttribute(fused_gemm, cudaFuncAttributeMaxDynamicSharedMemorySize,
                             FUSED_SMEM);
        attr_done = true;
    }

    prep_kernel<<<288, 256>>>(W1, b1, W2, b2, Wout, aw);
    fused_gemm<<<M_TOK / 64, 128, FUSED_SMEM>>>(x_rgb, x_depth, out_rgb, bout, out_fus);
}

// round 14
// speedup vs baseline: 2.3633x; 1.0884x over previous
#include <cuda_runtime.h>
#include <cuda_fp16.h>
#include <math.h>
#include <stdint.h>

// Problem constants: B=8, N=4096, C=768, H=8, D=96
constexpr int M_TOK = 8 * 4096;   // 32768 tokens
constexpr int K_IN  = 768;        // C

// ---- device scratch (allocation-free rule: __device__ globals) ----
__device__ __align__(16) __half g_Wr[96 * 768];   // fp16(w1 * sum_h Wv_rgb)
__device__ __align__(16) __half g_Wd[96 * 768];   // fp16(w0 * sum_h Wv_depth)
__device__ __align__(16) __half g_Wf[768 * 96];   // fp16(sum_q Wout folded)
__device__ float g_bg[96];                         // combined bias for g

// ============================================================
// Helpers (plain sm_103-safe PTX: ldmatrix + mma.sync + cp.async)
// ============================================================
__device__ __forceinline__ uint32_t smem_u32(const void* p) {
    uint32_t a;
    asm("{ .reg .u64 t; cvta.to.shared.u64 t, %1; cvt.u32.u64 %0, t; }" : "=r"(a) : "l"(p));
    return a;
}
__device__ __forceinline__ void ldsm4(uint32_t* r, uint32_t addr) {
    asm volatile("ldmatrix.sync.aligned.m8n8.x4.shared.b16 {%0,%1,%2,%3}, [%4];"
                 : "=r"(r[0]), "=r"(r[1]), "=r"(r[2]), "=r"(r[3]) : "r"(addr));
}
__device__ __forceinline__ void mma16816(float* c, const uint32_t* a, const uint32_t* b) {
    asm("mma.sync.aligned.m16n8k16.row.col.f32.f16.f16.f32 "
        "{%0,%1,%2,%3}, {%4,%5,%6,%7}, {%8,%9}, {%0,%1,%2,%3};"
        : "+f"(c[0]), "+f"(c[1]), "+f"(c[2]), "+f"(c[3])
        : "r"(a[0]), "r"(a[1]), "r"(a[2]), "r"(a[3]), "r"(b[0]), "r"(b[1]));
}
__device__ __forceinline__ void cpa16(uint32_t d, const void* s) {
    asm volatile("cp.async.cg.shared.global [%0], [%1], 16;" :: "r"(d), "l"(s));
}
#define CPA_COMMIT() asm volatile("cp.async.commit_group;" ::: "memory")
#define CPA_WAIT0()  asm volatile("cp.async.wait_group 0;" ::: "memory")

// Pack TWO floats into one fp16x2 (RN).
__device__ __forceinline__ uint32_t pack2h(float x, float y) {
    __half2 h = __floats2half2_rn(x, y);
    return *reinterpret_cast<uint32_t*>(&h);
}
// XOR swizzle on 16B chunks: conflict-free ldmatrix for 64B/192B rows
__device__ __forceinline__ uint32_t swz(uint32_t row, uint32_t chunk) {
    return chunk ^ ((row >> 1) & 3);
}

// ============================================================
// Prep: fold heads, sigmoid weights, round to fp16 (RN)
// ============================================================
__global__ void prep_kernel(const float* __restrict__ W1, const float* __restrict__ b1,
                            const float* __restrict__ W2, const float* __restrict__ b2,
                            const float* __restrict__ Wout, const float* __restrict__ aw)
{
    int idx = blockIdx.x * blockDim.x + threadIdx.x;   // 0 .. 73727
    float w0 = 1.0f / (1.0f + expf(-aw[0]));
    float w1 = 1.0f / (1.0f + expf(-aw[1]));

    if (idx < 96 * 768) {
        int d = idx / 768;
        int c = idx - d * 768;
        float sr = 0.0f, sd = 0.0f;
#pragma unroll
        for (int h = 0; h < 8; h++) {
            sr += W1[(size_t)(1536 + h * 96 + d) * 768 + c];
            sd += W2[(size_t)(768  + h * 96 + d) * 768 + c];
        }
        g_Wr[idx] = __float2half_rn(w1 * sr);
        g_Wd[idx] = __float2half_rn(w0 * sd);
    }
    if (idx < 768 * 96) {
        int c = idx / 96;
        int d = idx - c * 96;
        float s = 0.0f;
#pragma unroll
        for (int q = 0; q < 8; q++) s += Wout[(size_t)c * 768 + q * 96 + d];
        g_Wf[idx] = __float2half_rn(s);
    }
    if (idx < 96) {
        float sbr = 0.0f, sbd = 0.0f;
#pragma unroll
        for (int h = 0; h < 8; h++) {
            sbr += b1[1536 + h * 96 + idx];
            sbd += b2[768  + h * 96 + idx];
        }
        g_bg[idx] = w0 * sbd + w1 * sbr;
    }
}

// ============================================================
// FUSED kernel. R13: FULL single-term fp16 (A, B, G all one fp16).
// CTA 64x96, 128 threads (4 warps, warp tile 32x48), occ 4,
// grid 512 -> one wave over 148 SMs.
//  Phase 1: G = Xr@Wr^T + Xd@Wd^T + bg (48 stages of BK=32)
//           + fused x_rgb passthrough. G kept in SMEM (fp16).
//  Phase 2: Y = G @ Wf^T + bout, 12 Wf tiles of 64 cols.
// smem/CTA: phase1 2x10240=20480 | phase2 12K G + 2x12K B = 36864.
// ============================================================
constexpr uint32_t GST = 10240;                  // A 4K | B 6K
constexpr uint32_t G_B = 4096;
constexpr int G_STAGES = 48;                     // 1536 / 32

constexpr uint32_t P2_B   = 12288;   // B buffers start (G at [0,12288))
constexpr uint32_t P2_BSZ = 12288;   // per B buffer: 64 Wf rows x 192B
constexpr int FUSED_SMEM  = 36864;

__global__ __launch_bounds__(128, 4) void fused_gemm(const float* __restrict__ Xr,
                                                     const float* __restrict__ Xd,
                                                     float* __restrict__ out_rgb,
                                                     const float* __restrict__ bout,
                                                     float* __restrict__ Y)
{
    extern __shared__ char dsm[];
    const uint32_t sbase = smem_u32(dsm);

    const int tid   = threadIdx.x;
    const int lane  = tid & 31;
    const int wid   = tid >> 5;
    const int warpM = wid >> 1;      // 0..1 (32-row slices)
    const int warpN = wid & 1;       // 0..1 (48-col slices)
    const int bm    = blockIdx.x << 6;   // 64 rows per CTA

    // ======================= PHASE 1 =======================
    float acc[2][6][4];
#pragma unroll
    for (int i = 0; i < 2; i++)
#pragma unroll
        for (int j = 0; j < 6; j++)
#pragma unroll
            for (int q = 0; q < 4; q++) acc[i][j][q] = 0.0f;

    const int arow0 = tid >> 3;          // + 16*l, l<4  (A: 64 rows x 8 float4-cols)
    const int ac4   = tid & 7;

    // swz invariant under row += 16
    const uint32_t a_sts_sw = (swz((uint32_t)arow0, (uint32_t)(ac4 >> 1)) << 4) + (ac4 & 1) * 8;

    const uint32_t a_row = (uint32_t)(warpM * 32 + (lane & 15));
    const uint32_t a_ck0 = (uint32_t)(lane >> 4);
    const uint32_t b_row = (uint32_t)(warpN * 48 + (lane & 7) + ((lane >> 4) << 3));
    const uint32_t b_ck0 = (uint32_t)((lane >> 3) & 1);

    float4 av[4];

    // ---- prologue: stage 0 (rgb, kb = 0) ----
#pragma unroll
    for (int l = 0; l < 4; l++)
        av[l] = *reinterpret_cast<const float4*>(
            Xr + (size_t)(bm + arow0 + 16 * l) * 768 + (ac4 << 2));
    // B stage 0: 96 rows x 4 16B-chunks = 384 cpa16, 3/thread
#pragma unroll
    for (int l = 0; l < 3; l++) {
        int f = tid + (l << 7);
        uint32_t r = (uint32_t)(f >> 2), c = (uint32_t)(f & 3);
        cpa16(sbase + G_B + r * 64 + (swz(r, c) << 4),
              g_Wr + (size_t)r * 768 + (c << 3));
    }
    CPA_COMMIT();
#pragma unroll
    for (int l = 0; l < 4; l++) {
        uint32_t ro = (uint32_t)(arow0 + 16 * l) * 64;
        *reinterpret_cast<uint2*>(dsm + ro + a_sts_sw) =
            make_uint2(pack2h(av[l].x, av[l].y), pack2h(av[l].z, av[l].w));
        *reinterpret_cast<float4*>(
            out_rgb + (size_t)(bm + arow0 + 16 * l) * 768 + (ac4 << 2)) = av[l];
    }
    CPA_WAIT0();
    __syncthreads();

    for (int s = 0; s < G_STAGES; s++) {
        const int sn = s + 1;
        if (sn < G_STAGES) {
            const float* X = (sn < 24) ? Xr : Xd;
            const __half* BW = (sn < 24) ? g_Wr : g_Wd;
            const int kb = ((sn < 24) ? sn : (sn - 24)) << 5;
            const uint32_t bo = (uint32_t)(sn & 1) * GST;
#pragma unroll
            for (int l = 0; l < 4; l++)
                av[l] = *reinterpret_cast<const float4*>(
                    X + (size_t)(bm + arow0 + 16 * l) * 768 + kb + (ac4 << 2));
#pragma unroll
            for (int l = 0; l < 3; l++) {
                int f = tid + (l << 7);
                uint32_t r = (uint32_t)(f >> 2), c = (uint32_t)(f & 3);
                cpa16(sbase + bo + G_B + r * 64 + (swz(r, c) << 4),
                      BW + (size_t)r * 768 + kb + (c << 3));
            }
            CPA_COMMIT();
        }

        // ---- compute stage s (single-term fp16) ----
        {
            const uint32_t sb = sbase + (uint32_t)(s & 1) * GST;
#pragma unroll
            for (int kk = 0; kk < 2; kk++) {
                uint32_t ah[2][4];
#pragma unroll
                for (int mt = 0; mt < 2; mt++) {
                    uint32_t row = a_row + mt * 16;
                    ldsm4(ah[mt], sb + row * 64 + (swz(row, kk * 2 + a_ck0) << 4));
                }
                uint32_t b2[3][4];
#pragma unroll
                for (int ng = 0; ng < 3; ng++) {
                    uint32_t row = b_row + ng * 16;
                    ldsm4(b2[ng], sb + G_B + row * 64 + (swz(row, kk * 2 + b_ck0) << 4));
                }
#pragma unroll
                for (int mt = 0; mt < 2; mt++)
#pragma unroll
                    for (int nt = 0; nt < 6; nt++)
                        mma16816(acc[mt][nt], ah[mt], &b2[nt >> 1][(nt & 1) * 2]);
            }
        }

        if (sn < G_STAGES) {
            char* st = dsm + (sn & 1) * GST;
            const int kb = ((sn < 24) ? sn : (sn - 24)) << 5;
#pragma unroll
            for (int l = 0; l < 4; l++) {
                uint32_t ro = (uint32_t)(arow0 + 16 * l) * 64;
                *reinterpret_cast<uint2*>(st + ro + a_sts_sw) =
                    make_uint2(pack2h(av[l].x, av[l].y), pack2h(av[l].z, av[l].w));
            }
            if (sn < 24) {
#pragma unroll
                for (int l = 0; l < 4; l++)
                    *reinterpret_cast<float4*>(
                        out_rgb + (size_t)(bm + arow0 + 16 * l) * 768 + kb + (ac4 << 2)) = av[l];
            }
            CPA_WAIT0();
        }
        __syncthreads();
    }

    // ============== PHASE 1 -> 2 TRANSITION ==============
    // Prefetch B tile 0 (Wf rows 0..63) into B buffer 0: 768 cpa16, 6/thread.
#pragma unroll
    for (int l = 0; l < 6; l++) {
        int f = tid + (l << 7);
        int r = f / 12, u = f - r * 12;
        cpa16(sbase + P2_B + (uint32_t)r * 192 + (swz((uint32_t)r, (uint32_t)u) << 4),
              g_Wf + (size_t)r * 96 + (u << 3));
    }
    CPA_COMMIT();

    // Write G block (fp16, bias added) into smem [0, 12288).
#pragma unroll
    for (int mt = 0; mt < 2; mt++) {
        uint32_t r0 = (uint32_t)(warpM * 32 + mt * 16 + (lane >> 2));
#pragma unroll
        for (int nt = 0; nt < 6; nt++) {
            int n = warpN * 48 + nt * 8 + (lane & 3) * 2;
            float b0 = g_bg[n], b1 = g_bg[n + 1];
            uint32_t u = (uint32_t)(warpN * 6 + nt);
            uint32_t off = (uint32_t)((lane & 3) << 2);
            uint32_t ad0 = r0 * 192 + (swz(r0, u) << 4) + off;
            uint32_t ad1 = (r0 + 8) * 192 + (swz(r0 + 8, u) << 4) + off;
            *reinterpret_cast<uint32_t*>(dsm + ad0) =
                pack2h(acc[mt][nt][0] + b0, acc[mt][nt][1] + b1);
            *reinterpret_cast<uint32_t*>(dsm + ad1) =
                pack2h(acc[mt][nt][2] + b0, acc[mt][nt][3] + b1);
        }
    }
    CPA_WAIT0();
    __syncthreads();

    // ======================= PHASE 2 =======================
    // 12 Wf tiles of 64 cols; warp tile 32 rows x 32 cols (nt=4).
    const uint32_t p2b_row = (uint32_t)(warpN * 32 + (lane & 7) + ((lane >> 4) << 3));
    const uint32_t p2b_ck0 = (uint32_t)((lane >> 3) & 1);

    for (int i = 0; i < 12; i++) {
        if (i + 1 < 12) {
            const int cn = (i + 1) << 6;
            const uint32_t bo = P2_B + (uint32_t)((i + 1) & 1) * P2_BSZ;
#pragma unroll
            for (int l = 0; l < 6; l++) {
                int f = tid + (l << 7);
                int r = f / 12, u = f - r * 12;
                cpa16(sbase + bo + (uint32_t)r * 192 + (swz((uint32_t)r, (uint32_t)u) << 4),
                      g_Wf + (size_t)(cn + r) * 96 + (u << 3));
            }
            CPA_COMMIT();
        }

        float acc2[2][4][4];
#pragma unroll
        for (int a = 0; a < 2; a++)
#pragma unroll
            for (int j = 0; j < 4; j++)
#pragma unroll
                for (int q = 0; q < 4; q++) acc2[a][j][q] = 0.0f;

        const uint32_t bbase = sbase + P2_B + (uint32_t)(i & 1) * P2_BSZ;
#pragma unroll
        for (int ks = 0; ks < 6; ks++) {
            uint32_t ah[2][4];
#pragma unroll
            for (int mt = 0; mt < 2; mt++) {
                uint32_t row = a_row + mt * 16;
                ldsm4(ah[mt], sbase + row * 192 + (swz(row, ks * 2 + a_ck0) << 4));
            }
            uint32_t b2[2][4];
#pragma unroll
            for (int ng = 0; ng < 2; ng++) {
                uint32_t row = p2b_row + ng * 16;
                ldsm4(b2[ng], bbase + row * 192 + (swz(row, ks * 2 + p2b_ck0) << 4));
            }
#pragma unroll
            for (int mt = 0; mt < 2; mt++)
#pragma unroll
                for (int nt = 0; nt < 4; nt++)
                    mma16816(acc2[mt][nt], ah[mt], &b2[nt >> 1][(nt & 1) * 2]);
        }

        // epilogue tile i
#pragma unroll
        for (int mt = 0; mt < 2; mt++) {
            int m0 = bm + warpM * 32 + mt * 16 + (lane >> 2);
#pragma unroll
            for (int nt = 0; nt < 4; nt++) {
                int n = (i << 6) + warpN * 32 + nt * 8 + (lane & 3) * 2;
                float b0 = bout[n], b1 = bout[n + 1];
                *reinterpret_cast<float2*>(Y + (size_t)m0 * 768 + n) =
                    make_float2(acc2[mt][nt][0] + b0, acc2[mt][nt][1] + b1);
                *reinterpret_cast<float2*>(Y + (size_t)(m0 + 8) * 768 + n) =
                    make_float2(acc2[mt][nt][2] + b0, acc2[mt][nt][3] + b1);
            }
        }

        if (i + 1 < 12) CPA_WAIT0();
        __syncthreads();
    }
}

// ============================================================
extern "C" void kernel_launch(void* const* d_in, const int* in_sizes, int n_in,
                              void* d_out, int out_size)
{
    const float* x_rgb   = (const float*)d_in[0];
    const float* x_depth = (const float*)d_in[1];
    const float* W1      = (const float*)d_in[2];
    const float* b1      = (const float*)d_in[3];
    const float* W2      = (const float*)d_in[4];
    const float* b2      = (const float*)d_in[5];
    const float* Wout    = (const float*)d_in[6];
    const float* bout    = (const float*)d_in[7];
    const float* aw      = (const float*)d_in[8];

    float* out_rgb = (float*)d_out;
    float* out_fus = out_rgb + (size_t)M_TOK * K_IN;   // second half: x_fusion

    static bool attr_done = false;
    if (!attr_done) {
        cudaFuncSetAttribute(fused_gemm, cudaFuncAttributeMaxDynamicSharedMemorySize,
                             FUSED_SMEM);
        attr_done = true;
    }

    prep_kernel<<<288, 256>>>(W1, b1, W2, b2, Wout, aw);
    fused_gemm<<<M_TOK / 64, 128, FUSED_SMEM>>>(x_rgb, x_depth, out_rgb, bout, out_fus);
}

// round 15
// speedup vs baseline: 2.3729x; 1.0040x over previous
#include <cuda_runtime.h>
#include <cuda_fp16.h>
#include <math.h>
#include <stdint.h>

// Problem constants: B=8, N=4096, C=768, H=8, D=96
constexpr int M_TOK = 8 * 4096;   // 32768 tokens
constexpr int K_IN  = 768;        // C

// ---- device scratch (allocation-free rule: __device__ globals) ----
__device__ __align__(16) __half g_Wr[96 * 768];   // fp16(w1 * sum_h Wv_rgb)
__device__ __align__(16) __half g_Wd[96 * 768];   // fp16(w0 * sum_h Wv_depth)
__device__ __align__(16) __half g_Wf[768 * 96];   // fp16(sum_q Wout folded)
__device__ float g_bg[96];                         // combined bias for g

// ============================================================
// Helpers (plain sm_103-safe PTX: ldmatrix + mma.sync + cp.async)
// ============================================================
__device__ __forceinline__ uint32_t smem_u32(const void* p) {
    uint32_t a;
    asm("{ .reg .u64 t; cvta.to.shared.u64 t, %1; cvt.u32.u64 %0, t; }" : "=r"(a) : "l"(p));
    return a;
}
__device__ __forceinline__ void ldsm4(uint32_t* r, uint32_t addr) {
    asm volatile("ldmatrix.sync.aligned.m8n8.x4.shared.b16 {%0,%1,%2,%3}, [%4];"
                 : "=r"(r[0]), "=r"(r[1]), "=r"(r[2]), "=r"(r[3]) : "r"(addr));
}
__device__ __forceinline__ void mma16816(float* c, const uint32_t* a, const uint32_t* b) {
    asm("mma.sync.aligned.m16n8k16.row.col.f32.f16.f16.f32 "
        "{%0,%1,%2,%3}, {%4,%5,%6,%7}, {%8,%9}, {%0,%1,%2,%3};"
        : "+f"(c[0]), "+f"(c[1]), "+f"(c[2]), "+f"(c[3])
        : "r"(a[0]), "r"(a[1]), "r"(a[2]), "r"(a[3]), "r"(b[0]), "r"(b[1]));
}
__device__ __forceinline__ void cpa16(uint32_t d, const void* s) {
    asm volatile("cp.async.cg.shared.global [%0], [%1], 16;" :: "r"(d), "l"(s));
}
#define CPA_COMMIT() asm volatile("cp.async.commit_group;" ::: "memory")
#define CPA_WAIT1()  asm volatile("cp.async.wait_group 1;" ::: "memory")
#define CPA_WAIT2()  asm volatile("cp.async.wait_group 2;" ::: "memory")

// Pack TWO floats into one fp16x2 (RN).
__device__ __forceinline__ uint32_t pack2h(float x, float y) {
    __half2 h = __floats2half2_rn(x, y);
    return *reinterpret_cast<uint32_t*>(&h);
}
// XOR swizzle on 16B chunks: conflict-free ldmatrix for 64B/192B rows
__device__ __forceinline__ uint32_t swz(uint32_t row, uint32_t chunk) {
    return chunk ^ ((row >> 1) & 3);
}

// ============================================================
// Prep: fold heads, sigmoid weights, round to fp16 (RN)
// ============================================================
__global__ void prep_kernel(const float* __restrict__ W1, const float* __restrict__ b1,
                            const float* __restrict__ W2, const float* __restrict__ b2,
                            const float* __restrict__ Wout, const float* __restrict__ aw)
{
    int idx = blockIdx.x * blockDim.x + threadIdx.x;   // 0 .. 73727
    float w0 = 1.0f / (1.0f + expf(-aw[0]));
    float w1 = 1.0f / (1.0f + expf(-aw[1]));

    if (idx < 96 * 768) {
        int d = idx / 768;
        int c = idx - d * 768;
        float sr = 0.0f, sd = 0.0f;
#pragma unroll
        for (int h = 0; h < 8; h++) {
            sr += W1[(size_t)(1536 + h * 96 + d) * 768 + c];
            sd += W2[(size_t)(768  + h * 96 + d) * 768 + c];
        }
        g_Wr[idx] = __float2half_rn(w1 * sr);
        g_Wd[idx] = __float2half_rn(w0 * sd);
    }
    if (idx < 768 * 96) {
        int c = idx / 96;
        int d = idx - c * 96;
        float s = 0.0f;
#pragma unroll
        for (int q = 0; q < 8; q++) s += Wout[(size_t)c * 768 + q * 96 + d];
        g_Wf[idx] = __float2half_rn(s);
    }
    if (idx < 96) {
        float sbr = 0.0f, sbd = 0.0f;
#pragma unroll
        for (int h = 0; h < 8; h++) {
            sbr += b1[1536 + h * 96 + idx];
            sbd += b2[768  + h * 96 + idx];
        }
        g_bg[idx] = w0 * sbd + w1 * sbr;
    }
}

// ============================================================
// FUSED kernel. R14: DEEP cp.async pipelines.
//  Phase 1: A double-buffered (LDG->convert->STS spans one compute
//           section), B ring of 4 stages (prefetch distance 3,
//           wait_group 2 -> ~3 compute sections of latency cover).
//  Phase 2: B ring of 3 buffers (distance 2, wait_group 1).
// CTA 64x96, 128 threads (4 warps, warp tile 32x48), occ 4.
// smem/CTA: phase1 A 2x4096 + B 4x6144 = 32768
//           phase2 G 12288 + B 3x12288 = 49152.
// ============================================================
constexpr uint32_t A_ST  = 4096;     // per A stage: 64 rows x 64B
constexpr uint32_t B_OFF = 8192;     // B ring base
constexpr uint32_t B_ST  = 6144;     // per B stage: 96 rows x 64B
constexpr int G_STAGES   = 48;       // 1536 / 32

constexpr uint32_t P2_B   = 12288;   // B ring start (G at [0,12288))
constexpr uint32_t P2_BSZ = 12288;   // per B buffer: 64 Wf rows x 192B
constexpr int FUSED_SMEM  = 49152;

__global__ __launch_bounds__(128, 4) void fused_gemm(const float* __restrict__ Xr,
                                                     const float* __restrict__ Xd,
                                                     float* __restrict__ out_rgb,
                                                     const float* __restrict__ bout,
                                                     float* __restrict__ Y)
{
    extern __shared__ char dsm[];
    const uint32_t sbase = smem_u32(dsm);

    const int tid   = threadIdx.x;
    const int lane  = tid & 31;
    const int wid   = tid >> 5;
    const int warpM = wid >> 1;      // 0..1 (32-row slices)
    const int warpN = wid & 1;       // 0..1 (48-col slices)
    const int bm    = blockIdx.x << 6;   // 64 rows per CTA

    // ======================= PHASE 1 =======================
    float acc[2][6][4];
#pragma unroll
    for (int i = 0; i < 2; i++)
#pragma unroll
        for (int j = 0; j < 6; j++)
#pragma unroll
            for (int q = 0; q < 4; q++) acc[i][j][q] = 0.0f;

    const int arow0 = tid >> 3;          // + 16*l, l<4  (A: 64 rows x 8 float4-cols)
    const int ac4   = tid & 7;

    const uint32_t a_sts_sw = (swz((uint32_t)arow0, (uint32_t)(ac4 >> 1)) << 4) + (ac4 & 1) * 8;

    const uint32_t a_row = (uint32_t)(warpM * 32 + (lane & 15));
    const uint32_t a_ck0 = (uint32_t)(lane >> 4);
    const uint32_t b_row = (uint32_t)(warpN * 48 + (lane & 7) + ((lane >> 4) << 3));
    const uint32_t b_ck0 = (uint32_t)((lane >> 3) & 1);

    // per-thread B cp.async geometry: 3 chunks/thread
    const uint32_t b_r = (uint32_t)(tid >> 2);        // +32*l
    const uint32_t b_c = (uint32_t)(tid & 3);

    float4 av[4];

    // ---- prologue: A stage 0; B stages 0,1,2 (3 groups) ----
#pragma unroll
    for (int l = 0; l < 4; l++)
        av[l] = *reinterpret_cast<const float4*>(
            Xr + (size_t)(bm + arow0 + 16 * l) * 768 + (ac4 << 2));
#pragma unroll
    for (int ps = 0; ps < 3; ps++) {
        const int kb = ps << 5;
        const uint32_t bo = B_OFF + (uint32_t)ps * B_ST;
#pragma unroll
        for (int l = 0; l < 3; l++) {
            uint32_t r = b_r + 32 * l;
            cpa16(sbase + bo + r * 64 + (swz(r, b_c) << 4),
                  g_Wr + (size_t)r * 768 + kb + (b_c << 3));
        }
        CPA_COMMIT();
    }
#pragma unroll
    for (int l = 0; l < 4; l++) {
        uint32_t ro = (uint32_t)(arow0 + 16 * l) * 64;
        *reinterpret_cast<uint2*>(dsm + ro + a_sts_sw) =
            make_uint2(pack2h(av[l].x, av[l].y), pack2h(av[l].z, av[l].w));
        *reinterpret_cast<float4*>(
            out_rgb + (size_t)(bm + arow0 + 16 * l) * 768 + (ac4 << 2)) = av[l];
    }
    CPA_WAIT2();            // B0 complete (B1,B2 may be in flight)
    __syncthreads();

    for (int s = 0; s < G_STAGES; s++) {
        const int sn = s + 1;
        // A prefetch (stage s+1) via LDG
        if (sn < G_STAGES) {
            const float* X = (sn < 24) ? Xr : Xd;
            const int kb = ((sn < 24) ? sn : (sn - 24)) << 5;
#pragma unroll
            for (int l = 0; l < 4; l++)
                av[l] = *reinterpret_cast<const float4*>(
                    X + (size_t)(bm + arow0 + 16 * l) * 768 + kb + (ac4 << 2));
        }
        // B prefetch (stage s+3) via cp.async; ALWAYS commit (empty ok)
        {
            const int sp = s + 3;
            if (sp < G_STAGES) {
                const __half* BW = (sp < 24) ? g_Wr : g_Wd;
                const int kb = ((sp < 24) ? sp : (sp - 24)) << 5;
                const uint32_t bo = B_OFF + (uint32_t)(sp & 3) * B_ST;
#pragma unroll
                for (int l = 0; l < 3; l++) {
                    uint32_t r = b_r + 32 * l;
                    cpa16(sbase + bo + r * 64 + (swz(r, b_c) << 4),
                          BW + (size_t)r * 768 + kb + (b_c << 3));
                }
            }
            CPA_COMMIT();
        }

        // ---- compute stage s ----
        {
            const uint32_t ab = sbase + (uint32_t)(s & 1) * A_ST;
            const uint32_t bb = sbase + B_OFF + (uint32_t)(s & 3) * B_ST;
#pragma unroll
            for (int kk = 0; kk < 2; kk++) {
                uint32_t ah[2][4];
#pragma unroll
                for (int mt = 0; mt < 2; mt++) {
                    uint32_t row = a_row + mt * 16;
                    ldsm4(ah[mt], ab + row * 64 + (swz(row, kk * 2 + a_ck0) << 4));
                }
                uint32_t b2[3][4];
#pragma unroll
                for (int ng = 0; ng < 3; ng++) {
                    uint32_t row = b_row + ng * 16;
                    ldsm4(b2[ng], bb + row * 64 + (swz(row, kk * 2 + b_ck0) << 4));
                }
#pragma unroll
                for (int mt = 0; mt < 2; mt++)
#pragma unroll
                    for (int nt = 0; nt < 6; nt++)
                        mma16816(acc[mt][nt], ah[mt], &b2[nt >> 1][(nt & 1) * 2]);
            }
        }

        // A STS (stage s+1) + passthrough
        if (sn < G_STAGES) {
            char* st = dsm + (sn & 1) * A_ST;
            const int kb = ((sn < 24) ? sn : (sn - 24)) << 5;
#pragma unroll
            for (int l = 0; l < 4; l++) {
                uint32_t ro = (uint32_t)(arow0 + 16 * l) * 64;
                *reinterpret_cast<uint2*>(st + ro + a_sts_sw) =
                    make_uint2(pack2h(av[l].x, av[l].y), pack2h(av[l].z, av[l].w));
            }
            if (sn < 24) {
#pragma unroll
                for (int l = 0; l < 4; l++)
                    *reinterpret_cast<float4*>(
                        out_rgb + (size_t)(bm + arow0 + 16 * l) * 768 + kb + (ac4 << 2)) = av[l];
            }
        }
        CPA_WAIT2();        // B(s+1) complete (last 2 groups = s+2, s+3 may fly)
        __syncthreads();
    }

    // ============== PHASE 1 -> 2 TRANSITION ==============
    // Prefetch Wf tiles 0 and 1 into B ring buffers 0,1 (two groups).
#pragma unroll
    for (int pt = 0; pt < 2; pt++) {
        const int cn = pt << 6;
        const uint32_t bo = P2_B + (uint32_t)pt * P2_BSZ;
#pragma unroll
        for (int l = 0; l < 6; l++) {
            int f = tid + (l << 7);
            int r = f / 12, u = f - r * 12;
            cpa16(sbase + bo + (uint32_t)r * 192 + (swz((uint32_t)r, (uint32_t)u) << 4),
                  g_Wf + (size_t)(cn + r) * 96 + (u << 3));
        }
        CPA_COMMIT();
    }

    // Write G block (fp16, bias added) into smem [0, 12288).
#pragma unroll
    for (int mt = 0; mt < 2; mt++) {
        uint32_t r0 = (uint32_t)(warpM * 32 + mt * 16 + (lane >> 2));
#pragma unroll
        for (int nt = 0; nt < 6; nt++) {
            int n = warpN * 48 + nt * 8 + (lane & 3) * 2;
            float b0 = g_bg[n], b1 = g_bg[n + 1];
            uint32_t u = (uint32_t)(warpN * 6 + nt);
            uint32_t off = (uint32_t)((lane & 3) << 2);
            uint32_t ad0 = r0 * 192 + (swz(r0, u) << 4) + off;
            uint32_t ad1 = (r0 + 8) * 192 + (swz(r0 + 8, u) << 4) + off;
            *reinterpret_cast<uint32_t*>(dsm + ad0) =
                pack2h(acc[mt][nt][0] + b0, acc[mt][nt][1] + b1);
            *reinterpret_cast<uint32_t*>(dsm + ad1) =
                pack2h(acc[mt][nt][2] + b0, acc[mt][nt][3] + b1);
        }
    }
    CPA_WAIT1();            // Wf tile 0 complete
    __syncthreads();

    // ======================= PHASE 2 =======================
    // 12 Wf tiles of 64 cols; warp tile 32 rows x 32 cols (nt=4).
    const uint32_t p2b_row = (uint32_t)(warpN * 32 + (lane & 7) + ((lane >> 4) << 3));
    const uint32_t p2b_ck0 = (uint32_t)((lane >> 3) & 1);

    for (int i = 0; i < 12; i++) {
        // prefetch tile i+2 into ring buffer (i+2)%3; ALWAYS commit
        {
            const int ip = i + 2;
            if (ip < 12) {
                const int cn = ip << 6;
                const uint32_t bo = P2_B + (uint32_t)(ip % 3) * P2_BSZ;
#pragma unroll
                for (int l = 0; l < 6; l++) {
                    int f = tid + (l << 7);
                    int r = f / 12, u = f - r * 12;
                    cpa16(sbase + bo + (uint32_t)r * 192 + (swz((uint32_t)r, (uint32_t)u) << 4),
                          g_Wf + (size_t)(cn + r) * 96 + (u << 3));
                }
            }
            CPA_COMMIT();
        }

        float acc2[2][4][4];
#pragma unroll
        for (int a = 0; a < 2; a++)
#pragma unroll
            for (int j = 0; j < 4; j++)
#pragma unroll
                for (int q = 0; q < 4; q++) acc2[a][j][q] = 0.0f;

        const uint32_t bbase = sbase + P2_B + (uint32_t)(i % 3) * P2_BSZ;
#pragma unroll
        for (int ks = 0; ks < 6; ks++) {
            uint32_t ah[2][4];
#pragma unroll
            for (int mt = 0; mt < 2; mt++) {
                uint32_t row = a_row + mt * 16;
                ldsm4(ah[mt], sbase + row * 192 + (swz(row, ks * 2 + a_ck0) << 4));
            }
            uint32_t b2[2][4];
#pragma unroll
            for (int ng = 0; ng < 2; ng++) {
                uint32_t row = p2b_row + ng * 16;
                ldsm4(b2[ng], bbase + row * 192 + (swz(row, ks * 2 + p2b_ck0) << 4));
            }
#pragma unroll
            for (int mt = 0; mt < 2; mt++)
#pragma unroll
                for (int nt = 0; nt < 4; nt++)
                    mma16816(acc2[mt][nt], ah[mt], &b2[nt >> 1][(nt & 1) * 2]);
        }

        // epilogue tile i
#pragma unroll
        for (int mt = 0; mt < 2; mt++) {
            int m0 = bm + warpM * 32 + mt * 16 + (lane >> 2);
#pragma unroll
            for (int nt = 0; nt < 4; nt++) {
                int n = (i << 6) + warpN * 32 + nt * 8 + (lane & 3) * 2;
                float b0 = bout[n], b1 = bout[n + 1];
                *reinterpret_cast<float2*>(Y + (size_t)m0 * 768 + n) =
                    make_float2(acc2[mt][nt][0] + b0, acc2[mt][nt][1] + b1);
                *reinterpret_cast<float2*>(Y + (size_t)(m0 + 8) * 768 + n) =
                    make_float2(acc2[mt][nt][2] + b0, acc2[mt][nt][3] + b1);
            }
        }

        CPA_WAIT1();        // tile i+1 complete (tile i+2 may fly)
        __syncthreads();
    }
}

// ============================================================
extern "C" void kernel_launch(void* const* d_in, const int* in_sizes, int n_in,
                              void* d_out, int out_size)
{
    const float* x_rgb   = (const float*)d_in[0];
    const float* x_depth = (const float*)d_in[1];
    const float* W1      = (const float*)d_in[2];
    const float* b1      = (const float*)d_in[3];
    const float* W2      = (const float*)d_in[4];
    const float* b2      = (const float*)d_in[5];
    const float* Wout    = (const float*)d_in[6];
    const float* bout    = (const float*)d_in[7];
    const float* aw      = (const float*)d_in[8];

    float* out_rgb = (float*)d_out;
    float* out_fus = out_rgb + (size_t)M_TOK * K_IN;   // second half: x_fusion

    static bool attr_done = false;
    if (!attr_done) {
        cudaFuncSetAttribute(fused_gemm, cudaFuncAttributeMaxDynamicSharedMemorySize,
                             FUSED_SMEM);
        attr_done = true;
    }

    prep_kernel<<<288, 256>>>(W1, b1, W2, b2, Wout, aw);
    fused_gemm<<<M_TOK / 64, 128, FUSED_SMEM>>>(x_rgb, x_depth, out_rgb, bout, out_fus);
}

// round 16
// speedup vs baseline: 2.7064x; 1.1405x over previous
#include <cuda_runtime.h>
#include <cuda_fp16.h>
#include <math.h>
#include <stdint.h>

// Problem constants: B=8, N=4096, C=768, H=8, D=96
constexpr int M_TOK = 8 * 4096;   // 32768 tokens
constexpr int K_IN  = 768;        // C

// ---- device scratch (allocation-free rule: __device__ globals) ----
__device__ __align__(16) __half g_Wr[96 * 768];   // fp16(w1 * sum_h Wv_rgb)
__device__ __align__(16) __half g_Wd[96 * 768];   // fp16(w0 * sum_h Wv_depth)
__device__ __align__(16) __half g_Wf[768 * 96];   // fp16(sum_q Wout folded)
__device__ float g_bg[96];                         // combined bias for g

// ============================================================
// Helpers (plain sm_103-safe PTX: ldmatrix + mma.sync + cp.async)
// ============================================================
__device__ __forceinline__ uint32_t smem_u32(const void* p) {
    uint32_t a;
    asm("{ .reg .u64 t; cvta.to.shared.u64 t, %1; cvt.u32.u64 %0, t; }" : "=r"(a) : "l"(p));
    return a;
}
__device__ __forceinline__ void ldsm4(uint32_t* r, uint32_t addr) {
    asm volatile("ldmatrix.sync.aligned.m8n8.x4.shared.b16 {%0,%1,%2,%3}, [%4];"
                 : "=r"(r[0]), "=r"(r[1]), "=r"(r[2]), "=r"(r[3]) : "r"(addr));
}
__device__ __forceinline__ void mma16816(float* c, const uint32_t* a, const uint32_t* b) {
    asm("mma.sync.aligned.m16n8k16.row.col.f32.f16.f16.f32 "
        "{%0,%1,%2,%3}, {%4,%5,%6,%7}, {%8,%9}, {%0,%1,%2,%3};"
        : "+f"(c[0]), "+f"(c[1]), "+f"(c[2]), "+f"(c[3])
        : "r"(a[0]), "r"(a[1]), "r"(a[2]), "r"(a[3]), "r"(b[0]), "r"(b[1]));
}
__device__ __forceinline__ void cpa16(uint32_t d, const void* s) {
    asm volatile("cp.async.cg.shared.global [%0], [%1], 16;" :: "r"(d), "l"(s));
}
#define CPA_COMMIT() asm volatile("cp.async.commit_group;" ::: "memory")
#define CPA_WAIT1()  asm volatile("cp.async.wait_group 1;" ::: "memory")

// Pack TWO floats into one fp16x2 (RN).
__device__ __forceinline__ uint32_t pack2h(float x, float y) {
    __half2 h = __floats2half2_rn(x, y);
    return *reinterpret_cast<uint32_t*>(&h);
}
// XOR swizzle on 16B chunks: conflict-free ldmatrix for 64B/192B rows
__device__ __forceinline__ uint32_t swz(uint32_t row, uint32_t chunk) {
    return chunk ^ ((row >> 1) & 3);
}

// ============================================================
// Prep: fold heads, sigmoid weights, round to fp16 (RN)
// ============================================================
__global__ void prep_kernel(const float* __restrict__ W1, const float* __restrict__ b1,
                            const float* __restrict__ W2, const float* __restrict__ b2,
                            const float* __restrict__ Wout, const float* __restrict__ aw)
{
    int idx = blockIdx.x * blockDim.x + threadIdx.x;   // 0 .. 73727
    float w0 = 1.0f / (1.0f + expf(-aw[0]));
    float w1 = 1.0f / (1.0f + expf(-aw[1]));

    if (idx < 96 * 768) {
        int d = idx / 768;
        int c = idx - d * 768;
        float sr = 0.0f, sd = 0.0f;
#pragma unroll
        for (int h = 0; h < 8; h++) {
            sr += W1[(size_t)(1536 + h * 96 + d) * 768 + c];
            sd += W2[(size_t)(768  + h * 96 + d) * 768 + c];
        }
        g_Wr[idx] = __float2half_rn(w1 * sr);
        g_Wd[idx] = __float2half_rn(w0 * sd);
    }
    if (idx < 768 * 96) {
        int c = idx / 96;
        int d = idx - c * 96;
        float s = 0.0f;
#pragma unroll
        for (int q = 0; q < 8; q++) s += Wout[(size_t)c * 768 + q * 96 + d];
        g_Wf[idx] = __float2half_rn(s);
    }
    if (idx < 96) {
        float sbr = 0.0f, sbd = 0.0f;
#pragma unroll
        for (int h = 0; h < 8; h++) {
            sbr += b1[1536 + h * 96 + idx];
            sbd += b2[768  + h * 96 + idx];
        }
        g_bg[idx] = w0 * sbd + w1 * sbr;
    }
}

// ============================================================
// FUSED kernel. R15: A staged through cp.async as RAW fp32
// (ring of 3, prefetch distance 2, joint commit group with B).
// The steady-state loop has NO LDG: convert is LDS->cvt->STS.
// CTA 64x96, 128 threads (4 warps, warp tile 32x48), occ 4.
// smem/CTA: A16 2x4096 | A32 3x8192 | B 3x6144 = 51200.
// Phase 2 reuses [0, 49152): G 12288 + B ring 3x12288.
// ============================================================
constexpr uint32_t A16_ST = 4096;            // per fp16 A stage (64 x 64B)
constexpr uint32_t A32    = 8192;            // fp32 A ring base
constexpr uint32_t A32_ST = 8192;            // per fp32 A stage (64 x 128B)
constexpr uint32_t B_OFF  = 32768;           // B ring base
constexpr uint32_t B_ST   = 6144;            // per B stage (96 x 64B)
constexpr int G_STAGES    = 48;              // 1536 / 32

constexpr uint32_t P2_B   = 12288;   // phase-2 B ring (G at [0,12288))
constexpr uint32_t P2_BSZ = 12288;   // per B buffer: 64 Wf rows x 192B
constexpr int FUSED_SMEM  = 51200;

__global__ __launch_bounds__(128, 4) void fused_gemm(const float* __restrict__ Xr,
                                                     const float* __restrict__ Xd,
                                                     float* __restrict__ out_rgb,
                                                     const float* __restrict__ bout,
                                                     float* __restrict__ Y)
{
    extern __shared__ char dsm[];
    const uint32_t sbase = smem_u32(dsm);

    const int tid   = threadIdx.x;
    const int lane  = tid & 31;
    const int wid   = tid >> 5;
    const int warpM = wid >> 1;      // 0..1 (32-row slices)
    const int warpN = wid & 1;       // 0..1 (48-col slices)
    const int bm    = blockIdx.x << 6;   // 64 rows per CTA

    // ======================= PHASE 1 =======================
    float acc[2][6][4];
#pragma unroll
    for (int i = 0; i < 2; i++)
#pragma unroll
        for (int j = 0; j < 6; j++)
#pragma unroll
            for (int q = 0; q < 4; q++) acc[i][j][q] = 0.0f;

    const int arow0 = tid >> 3;          // + 16*l, l<4  (A: 64 rows x 8 chunk-cols)
    const int ac4   = tid & 7;

    const uint32_t a_sts_sw = (swz((uint32_t)arow0, (uint32_t)(ac4 >> 1)) << 4) + (ac4 & 1) * 8;

    const uint32_t a_row = (uint32_t)(warpM * 32 + (lane & 15));
    const uint32_t a_ck0 = (uint32_t)(lane >> 4);
    const uint32_t b_row = (uint32_t)(warpN * 48 + (lane & 7) + ((lane >> 4) << 3));
    const uint32_t b_ck0 = (uint32_t)((lane >> 3) & 1);

    // B cp.async geometry: 3 chunks/thread
    const uint32_t b_r = (uint32_t)(tid >> 2);        // +32*l
    const uint32_t b_c = (uint32_t)(tid & 3);

    // A-fp32 cp.async geometry: f = tid + 128*l -> row f>>3, chunk f&7.
    // (Self-mapping: the convert step reads back exactly these chunks.)

    // ---- prologue: commit groups for stages 0 and 1 ----
#pragma unroll
    for (int ps = 0; ps < 2; ps++) {
        const int kb = ps << 5;
        const uint32_t ao = A32 + (uint32_t)ps * A32_ST;
        const uint32_t bo = B_OFF + (uint32_t)ps * B_ST;
#pragma unroll
        for (int l = 0; l < 4; l++) {
            int f = tid + (l << 7);
            uint32_t r = (uint32_t)(f >> 3), c = (uint32_t)(f & 7);
            cpa16(sbase + ao + r * 128 + (c << 4),
                  Xr + (size_t)(bm + r) * 768 + kb + (c << 2));
        }
#pragma unroll
        for (int l = 0; l < 3; l++) {
            uint32_t r = b_r + 32 * l;
            cpa16(sbase + bo + r * 64 + (swz(r, b_c) << 4),
                  g_Wr + (size_t)r * 768 + kb + (b_c << 3));
        }
        CPA_COMMIT();
    }
    CPA_WAIT1();            // group 0 complete (group 1 in flight)
    // convert stage 0: A32 buf0 -> A16 buf0, + passthrough STG
#pragma unroll
    for (int l = 0; l < 4; l++) {
        uint32_t row = (uint32_t)(arow0 + 16 * l);
        float4 v = *reinterpret_cast<const float4*>(dsm + A32 + row * 128 + (ac4 << 4));
        *reinterpret_cast<uint2*>(dsm + row * 64 + a_sts_sw) =
            make_uint2(pack2h(v.x, v.y), pack2h(v.z, v.w));
        *reinterpret_cast<float4*>(
            out_rgb + (size_t)(bm + row) * 768 + (ac4 << 2)) = v;
    }
    __syncthreads();

    for (int s = 0; s < G_STAGES; s++) {
        // ---- commit cp.async group for stage s+2 (empty ok) ----
        {
            const int sp = s + 2;
            if (sp < G_STAGES) {
                const float* X = (sp < 24) ? Xr : Xd;
                const __half* BW = (sp < 24) ? g_Wr : g_Wd;
                const int kb = ((sp < 24) ? sp : (sp - 24)) << 5;
                const uint32_t ao = A32 + (uint32_t)(sp % 3) * A32_ST;
                const uint32_t bo = B_OFF + (uint32_t)(sp % 3) * B_ST;
#pragma unroll
                for (int l = 0; l < 4; l++) {
                    int f = tid + (l << 7);
                    uint32_t r = (uint32_t)(f >> 3), c = (uint32_t)(f & 7);
                    cpa16(sbase + ao + r * 128 + (c << 4),
                          X + (size_t)(bm + r) * 768 + kb + (c << 2));
                }
#pragma unroll
                for (int l = 0; l < 3; l++) {
                    uint32_t r = b_r + 32 * l;
                    cpa16(sbase + bo + r * 64 + (swz(r, b_c) << 4),
                          BW + (size_t)r * 768 + kb + (b_c << 3));
                }
            }
            CPA_COMMIT();
        }

        // ---- compute stage s ----
        {
            const uint32_t ab = sbase + (uint32_t)(s & 1) * A16_ST;
            const uint32_t bb = sbase + B_OFF + (uint32_t)(s % 3) * B_ST;
#pragma unroll
            for (int kk = 0; kk < 2; kk++) {
                uint32_t ah[2][4];
#pragma unroll
                for (int mt = 0; mt < 2; mt++) {
                    uint32_t row = a_row + mt * 16;
                    ldsm4(ah[mt], ab + row * 64 + (swz(row, kk * 2 + a_ck0) << 4));
                }
                uint32_t b2[3][4];
#pragma unroll
                for (int ng = 0; ng < 3; ng++) {
                    uint32_t row = b_row + ng * 16;
                    ldsm4(b2[ng], bb + row * 64 + (swz(row, kk * 2 + b_ck0) << 4));
                }
#pragma unroll
                for (int mt = 0; mt < 2; mt++)
#pragma unroll
                    for (int nt = 0; nt < 6; nt++)
                        mma16816(acc[mt][nt], ah[mt], &b2[nt >> 1][(nt & 1) * 2]);
            }
        }

        CPA_WAIT1();        // group s+1 complete (s+2 in flight)

        // ---- convert stage s+1: A32 -> A16 (+ passthrough STG) ----
        {
            const int sn = s + 1;
            if (sn < G_STAGES) {
                const uint32_t ao = A32 + (uint32_t)(sn % 3) * A32_ST;
                char* st = dsm + (sn & 1) * A16_ST;
                const int kb = ((sn < 24) ? sn : (sn - 24)) << 5;
#pragma unroll
                for (int l = 0; l < 4; l++) {
                    uint32_t row = (uint32_t)(arow0 + 16 * l);
                    float4 v = *reinterpret_cast<const float4*>(
                        dsm + ao + row * 128 + (ac4 << 4));
                    *reinterpret_cast<uint2*>(st + row * 64 + a_sts_sw) =
                        make_uint2(pack2h(v.x, v.y), pack2h(v.z, v.w));
                    if (sn < 24)
                        *reinterpret_cast<float4*>(
                            out_rgb + (size_t)(bm + row) * 768 + kb + (ac4 << 2)) = v;
                }
            }
        }
        __syncthreads();
    }

    // ============== PHASE 1 -> 2 TRANSITION ==============
    // Commit Wf tiles 0 and 1 into phase-2 B ring buffers 0,1.
#pragma unroll
    for (int pt = 0; pt < 2; pt++) {
        const int cn = pt << 6;
        const uint32_t bo = P2_B + (uint32_t)pt * P2_BSZ;
#pragma unroll
        for (int l = 0; l < 6; l++) {
            int f = tid + (l << 7);
            int r = f / 12, u = f - r * 12;
            cpa16(sbase + bo + (uint32_t)r * 192 + (swz((uint32_t)r, (uint32_t)u) << 4),
                  g_Wf + (size_t)(cn + r) * 96 + (u << 3));
        }
        CPA_COMMIT();
    }

    // Write G block (fp16, bias added) into smem [0, 12288).
#pragma unroll
    for (int mt = 0; mt < 2; mt++) {
        uint32_t r0 = (uint32_t)(warpM * 32 + mt * 16 + (lane >> 2));
#pragma unroll
        for (int nt = 0; nt < 6; nt++) {
            int n = warpN * 48 + nt * 8 + (lane & 3) * 2;
            float b0 = g_bg[n], b1 = g_bg[n + 1];
            uint32_t u = (uint32_t)(warpN * 6 + nt);
            uint32_t off = (uint32_t)((lane & 3) << 2);
            uint32_t ad0 = r0 * 192 + (swz(r0, u) << 4) + off;
            uint32_t ad1 = (r0 + 8) * 192 + (swz(r0 + 8, u) << 4) + off;
            *reinterpret_cast<uint32_t*>(dsm + ad0) =
                pack2h(acc[mt][nt][0] + b0, acc[mt][nt][1] + b1);
            *reinterpret_cast<uint32_t*>(dsm + ad1) =
                pack2h(acc[mt][nt][2] + b0, acc[mt][nt][3] + b1);
        }
    }
    CPA_WAIT1();            // Wf tile 0 complete
    __syncthreads();

    // ======================= PHASE 2 =======================
    // 12 Wf tiles of 64 cols; warp tile 32 rows x 32 cols (nt=4).
    const uint32_t p2b_row = (uint32_t)(warpN * 32 + (lane & 7) + ((lane >> 4) << 3));
    const uint32_t p2b_ck0 = (uint32_t)((lane >> 3) & 1);

    for (int i = 0; i < 12; i++) {
        // commit tile i+2 into ring buffer (i+2)%3 (empty ok)
        {
            const int ip = i + 2;
            if (ip < 12) {
                const int cn = ip << 6;
                const uint32_t bo = P2_B + (uint32_t)(ip % 3) * P2_BSZ;
#pragma unroll
                for (int l = 0; l < 6; l++) {
                    int f = tid + (l << 7);
                    int r = f / 12, u = f - r * 12;
                    cpa16(sbase + bo + (uint32_t)r * 192 + (swz((uint32_t)r, (uint32_t)u) << 4),
                          g_Wf + (size_t)(cn + r) * 96 + (u << 3));
                }
            }
            CPA_COMMIT();
        }

        float acc2[2][4][4];
#pragma unroll
        for (int a = 0; a < 2; a++)
#pragma unroll
            for (int j = 0; j < 4; j++)
#pragma unroll
                for (int q = 0; q < 4; q++) acc2[a][j][q] = 0.0f;

        const uint32_t bbase = sbase + P2_B + (uint32_t)(i % 3) * P2_BSZ;
#pragma unroll
        for (int ks = 0; ks < 6; ks++) {
            uint32_t ah[2][4];
#pragma unroll
            for (int mt = 0; mt < 2; mt++) {
                uint32_t row = a_row + mt * 16;
                ldsm4(ah[mt], sbase + row * 192 + (swz(row, ks * 2 + a_ck0) << 4));
            }
            uint32_t b2[2][4];
#pragma unroll
            for (int ng = 0; ng < 2; ng++) {
                uint32_t row = p2b_row + ng * 16;
                ldsm4(b2[ng], bbase + row * 192 + (swz(row, ks * 2 + p2b_ck0) << 4));
            }
#pragma unroll
            for (int mt = 0; mt < 2; mt++)
#pragma unroll
                for (int nt = 0; nt < 4; nt++)
                    mma16816(acc2[mt][nt], ah[mt], &b2[nt >> 1][(nt & 1) * 2]);
        }

        // epilogue tile i
#pragma unroll
        for (int mt = 0; mt < 2; mt++) {
            int m0 = bm + warpM * 32 + mt * 16 + (lane >> 2);
#pragma unroll
            for (int nt = 0; nt < 4; nt++) {
                int n = (i << 6) + warpN * 32 + nt * 8 + (lane & 3) * 2;
                float b0 = bout[n], b1 = bout[n + 1];
                *reinterpret_cast<float2*>(Y + (size_t)m0 * 768 + n) =
                    make_float2(acc2[mt][nt][0] + b0, acc2[mt][nt][1] + b1);
                *reinterpret_cast<float2*>(Y + (size_t)(m0 + 8) * 768 + n) =
                    make_float2(acc2[mt][nt][2] + b0, acc2[mt][nt][3] + b1);
            }
        }

        CPA_WAIT1();        // tile i+1 complete (tile i+2 may fly)
        __syncthreads();
    }
}

// ============================================================
extern "C" void kernel_launch(void* const* d_in, const int* in_sizes, int n_in,
                              void* d_out, int out_size)
{
    const float* x_rgb   = (const float*)d_in[0];
    const float* x_depth = (const float*)d_in[1];
    const float* W1      = (const float*)d_in[2];
    const float* b1      = (const float*)d_in[3];
    const float* W2      = (const float*)d_in[4];
    const float* b2      = (const float*)d_in[5];
    const float* Wout    = (const float*)d_in[6];
    const float* bout    = (const float*)d_in[7];
    const float* aw      = (const float*)d_in[8];

    float* out_rgb = (float*)d_out;
    float* out_fus = out_rgb + (size_t)M_TOK * K_IN;   // second half: x_fusion

    static bool attr_done = false;
    if (!attr_done) {
        cudaFuncSetAttribute(fused_gemm, cudaFuncAttributeMaxDynamicSharedMemorySize,
                             FUSED_SMEM);
        attr_done = true;
    }

    prep_kernel<<<288, 256>>>(W1, b1, W2, b2, Wout, aw);
    fused_gemm<<<M_TOK / 64, 128, FUSED_SMEM>>>(x_rgb, x_depth, out_rgb, bout, out_fus);
}